// round 10
// baseline (speedup 1.0000x reference)
#include <cuda_runtime.h>
#include <cuda_bf16.h>
#include <cstdint>

#define NN  100000
#define NE  500000
#define H   128
#define D_U 256
#define D_I 300
#define NUH (NN * H)
#define SCAN_NB 98            // ceil(NN/1024)

// ---------------- scratch (static device globals; no allocation) -------------
__device__ float g_hu[2][NUH];
__device__ float g_hi[2][NUH];
__device__ float g_deg[6][NN];     // rsqrt: 0 out_uu, 1 in_uu, 2 out_ui, 3 in_ui, 4 out_iu, 5 in_iu
__device__ int   g_degi[6][NN];
__device__ int   g_off[3][NN];     // CSR row starts per etype: 0=uu, 1=ui, 2=iu
__device__ int   g_cur[3][NN];
__device__ int   g_esrc[3][NE];    // edge src sorted by dst
__device__ int   g_bsum[3][128];

// ---------------- small helpers ----------------------------------------------
__device__ __forceinline__ uint32_t smem_u32(const void* p) {
    uint32_t a;
    asm("{ .reg .u64 t; cvta.to.shared.u64 t, %1; cvt.u32.u64 %0, t; }" : "=r"(a) : "l"(p));
    return a;
}
__device__ __forceinline__ void ldm_x4(uint32_t* r, uint32_t addr) {
    asm volatile("ldmatrix.sync.aligned.m8n8.x4.shared.b16 {%0,%1,%2,%3}, [%4];"
                 : "=r"(r[0]), "=r"(r[1]), "=r"(r[2]), "=r"(r[3]) : "r"(addr));
}
__device__ __forceinline__ void ldm_x4_t(uint32_t* r, uint32_t addr) {
    asm volatile("ldmatrix.sync.aligned.m8n8.x4.trans.shared.b16 {%0,%1,%2,%3}, [%4];"
                 : "=r"(r[0]), "=r"(r[1]), "=r"(r[2]), "=r"(r[3]) : "r"(addr));
}
__device__ __forceinline__ void mma_bf16(float* d, const uint32_t* a, uint32_t b0, uint32_t b1) {
    asm volatile("mma.sync.aligned.m16n8k16.row.col.f32.bf16.bf16.f32 "
                 "{%0,%1,%2,%3}, {%4,%5,%6,%7}, {%8,%9}, {%0,%1,%2,%3};"
                 : "+f"(d[0]), "+f"(d[1]), "+f"(d[2]), "+f"(d[3])
                 : "r"(a[0]), "r"(a[1]), "r"(a[2]), "r"(a[3]), "r"(b0), "r"(b1));
}
__device__ __forceinline__ void split2(float a, float b, uint32_t& hi, float& ra, float& rb) {
    __nv_bfloat16 ha = __float2bfloat16(a), hb = __float2bfloat16(b);
    hi = (uint32_t)__bfloat16_as_ushort(ha) | ((uint32_t)__bfloat16_as_ushort(hb) << 16);
    ra = a - __bfloat162float(ha);
    rb = b - __bfloat162float(hb);
}
__device__ __forceinline__ uint32_t pack2(float a, float b) {
    return (uint32_t)__bfloat16_as_ushort(__float2bfloat16(a)) |
           ((uint32_t)__bfloat16_as_ushort(__float2bfloat16(b)) << 16);
}

// ---------------- setup kernels ----------------------------------------------
__global__ void zero_int_kernel(int* p, int n) {
    int i = blockIdx.x * blockDim.x + threadIdx.x;
    int stride = gridDim.x * blockDim.x;
    for (; i < n; i += stride) p[i] = 0;
}

__global__ void deg_count_kernel(const int* __restrict__ suu, const int* __restrict__ duu,
                                 const int* __restrict__ sui, const int* __restrict__ dui,
                                 const int* __restrict__ siu, const int* __restrict__ diu,
                                 int* __restrict__ degi) {
    int i = blockIdx.x * blockDim.x + threadIdx.x;
    if (i >= NE) return;
    atomicAdd(&degi[0 * NN + suu[i]], 1);
    atomicAdd(&degi[1 * NN + duu[i]], 1);
    atomicAdd(&degi[2 * NN + sui[i]], 1);
    atomicAdd(&degi[3 * NN + dui[i]], 1);
    atomicAdd(&degi[4 * NN + siu[i]], 1);
    atomicAdd(&degi[5 * NN + diu[i]], 1);
}

__global__ void deg_finalize_kernel(const int* __restrict__ degi, float* __restrict__ deg) {
    int i = blockIdx.x * blockDim.x + threadIdx.x;
    if (i >= NN) return;
#pragma unroll
    for (int j = 0; j < 6; j++)
        deg[j * NN + i] = rsqrtf(fmaxf((float)degi[j * NN + i], 1.f));
}

__global__ void scan_s1(const int* __restrict__ degi, int* __restrict__ off,
                        int* __restrict__ bsum) {
    int et = blockIdx.y;
    const int* d = degi + (1 + 2 * et) * NN;
    int* o = off + et * NN;
    __shared__ int wsum[8], woff[8];
    int t = threadIdx.x;
    int base = blockIdx.x * 1024 + t * 4;
    int x[4];
#pragma unroll
    for (int j = 0; j < 4; j++) x[j] = (base + j < NN) ? d[base + j] : 0;
    int tl = x[0] + x[1] + x[2] + x[3];
    int incl = tl;
#pragma unroll
    for (int s = 1; s < 32; s <<= 1) {
        int y = __shfl_up_sync(0xffffffff, incl, s);
        if ((t & 31) >= s) incl += y;
    }
    if ((t & 31) == 31) wsum[t >> 5] = incl;
    __syncthreads();
    if (t == 0) {
        int a = 0;
#pragma unroll
        for (int k = 0; k < 8; k++) { woff[k] = a; a += wsum[k]; }
    }
    __syncthreads();
    int run = woff[t >> 5] + incl - tl;
#pragma unroll
    for (int j = 0; j < 4; j++) {
        if (base + j < NN) o[base + j] = run;
        run += x[j];
    }
    if (t == 255) bsum[et * 128 + blockIdx.x] = woff[7] + wsum[7];
}

__global__ void scan_s2(int* bsum) {
    int et = threadIdx.x;
    if (et < 3) {
        int a = 0;
        for (int i = 0; i < SCAN_NB; i++) {
            int t = bsum[et * 128 + i];
            bsum[et * 128 + i] = a;
            a += t;
        }
    }
}

__global__ void scan_s3(int* __restrict__ off, const int* __restrict__ bsum) {
    int et = blockIdx.y;
    int i = blockIdx.x * blockDim.x + threadIdx.x;
    if (i < NN) off[et * NN + i] += bsum[et * 128 + (i >> 10)];
}

__global__ void fill_kernel(const int* __restrict__ src, const int* __restrict__ dst,
                            const int* __restrict__ off, int* __restrict__ cur,
                            int* __restrict__ esrc) {
    int e = blockIdx.x * blockDim.x + threadIdx.x;
    if (e >= NE) return;
    int d = dst[e];
    int p = atomicAdd(&cur[d], 1);
    esrc[off[d] + p] = src[e];
}

// ---------------- dense bf16x3 GEMM (embeds; any K) ---------------------------
#define BMROWS 64
#define ABUF 5120                  // 64 rows * 80B
#define BBUF 8192                  // 32 k-rows * 256B
#define BUFSZ (2 * ABUF + 2 * BBUF)
#define SM_BIAS (2 * BUFSZ)
#define TCSMEM (SM_BIAS + 512)

__global__ __launch_bounds__(256, 3) void mma_gemm_kernel(
    const float* __restrict__ A, const float* __restrict__ W,
    const float* __restrict__ bias,
    float* __restrict__ C, int M, int K)
{
    extern __shared__ char sm[];
    const uint32_t sbase = smem_u32(sm);
    const int tid = threadIdx.x, lane = tid & 31, wid = tid >> 5;
    const int blockRow = blockIdx.x * BMROWS;
    const int wm = (wid & 3) * 16;
    const int wn = (wid >> 2) * 64;

    if (tid < 128) ((float*)(sm + SM_BIAS))[tid] = bias[tid];

    float acc[8][4];
#pragma unroll
    for (int j = 0; j < 8; j++)
#pragma unroll
        for (int k = 0; k < 4; k++) acc[j][k] = 0.f;

    const int nch = (K + 31) / 32;

    const int r8 = lane & 7, sel = lane >> 3;
    const int a_row = r8 + ((sel & 1) << 3);
    const int a_kb  = (sel >> 1) << 4;
    const int b_csel = sel >> 1;

    auto load_chunk = [&](int ch) {
        const int k0 = ch * 32;
        char* buf = sm + (ch & 1) * BUFSZ;
#pragma unroll
        for (int i = 0; i < 2; i++) {
            int idx = tid + i * 256;
            int row = idx >> 3, q = idx & 7;
            int gm = blockRow + row, gk = k0 + q * 4;
            float4 v = make_float4(0.f, 0.f, 0.f, 0.f);
            if (gm < M) {
                const float* ap = A + (size_t)gm * K + gk;
                if (gk + 3 < K) v = *(const float4*)ap;
                else {
                    if (gk + 0 < K) v.x = ap[0];
                    if (gk + 1 < K) v.y = ap[1];
                    if (gk + 2 < K) v.z = ap[2];
                    if (gk + 3 < K) v.w = ap[3];
                }
            }
            float rx, ry, rz, rw;
            uint2 hi, lo;
            split2(v.x, v.y, hi.x, rx, ry);
            split2(v.z, v.w, hi.y, rz, rw);
            lo.x = pack2(rx, ry);
            lo.y = pack2(rz, rw);
            *(uint2*)(buf + (size_t)row * 80 + q * 8) = hi;
            *(uint2*)(buf + ABUF + (size_t)row * 80 + q * 8) = lo;
        }
#pragma unroll
        for (int i = 0; i < 4; i++) {
            int idx = tid + i * 256;
            int kk = idx >> 5, q = idx & 31;
            int gk = k0 + kk;
            float4 v = make_float4(0.f, 0.f, 0.f, 0.f);
            if (gk < K) v = *(const float4*)(W + (size_t)gk * 128 + q * 4);
            float rx, ry, rz, rw;
            uint2 hi, lo;
            split2(v.x, v.y, hi.x, rx, ry);
            split2(v.z, v.w, hi.y, rz, rw);
            lo.x = pack2(rx, ry);
            lo.y = pack2(rz, rw);
            uint32_t o = (uint32_t)kk * 256 + ((((uint32_t)(q >> 1)) ^ (kk & 7)) << 4) + (q & 1) * 8;
            *(uint2*)(buf + 2 * ABUF + o) = hi;
            *(uint2*)(buf + 2 * ABUF + BBUF + o) = lo;
        }
    };

    load_chunk(0);
    __syncthreads();

    for (int ch = 0; ch < nch; ch++) {
        if (ch + 1 < nch) load_chunk(ch + 1);
        const uint32_t bufb = sbase + (ch & 1) * BUFSZ;

#pragma unroll
        for (int h = 0; h < 2; h++) {
            uint32_t ah[4], al[4], bf[4][4];
            {
                uint32_t aaddr = bufb + (wm + a_row) * 80 + h * 32 + a_kb;
                ldm_x4(ah, aaddr);
                ldm_x4(al, aaddr + ABUF);
            }
            const int kk = h * 16 + a_row;
            const uint32_t brow = bufb + 2 * ABUF + (uint32_t)kk * 256;
#pragma unroll
            for (int j = 0; j < 4; j++) {
                uint32_t chunk = (uint32_t)((wn >> 3) + j * 2 + b_csel) ^ (kk & 7);
                ldm_x4_t(bf[j], brow + chunk * 16);
            }
#pragma unroll
            for (int j = 0; j < 4; j++) {
                mma_bf16(acc[2 * j],     ah, bf[j][0], bf[j][1]);
                mma_bf16(acc[2 * j + 1], ah, bf[j][2], bf[j][3]);
                mma_bf16(acc[2 * j],     al, bf[j][0], bf[j][1]);
                mma_bf16(acc[2 * j + 1], al, bf[j][2], bf[j][3]);
            }
#pragma unroll
            for (int j = 0; j < 4; j++) {
                uint32_t chunk = (uint32_t)((wn >> 3) + j * 2 + b_csel) ^ (kk & 7);
                ldm_x4_t(bf[j], brow + BBUF + chunk * 16);
            }
#pragma unroll
            for (int j = 0; j < 4; j++) {
                mma_bf16(acc[2 * j],     ah, bf[j][0], bf[j][1]);
                mma_bf16(acc[2 * j + 1], ah, bf[j][2], bf[j][3]);
            }
        }
        __syncthreads();
    }

    const float* bs = (const float*)(sm + SM_BIAS);
    const int g = lane >> 2;
    const int t2 = (lane & 3) * 2;
#pragma unroll
    for (int half = 0; half < 2; half++) {
        int row = blockRow + wm + g + half * 8;
        if (row >= M) continue;
        float* cp = C + (size_t)row * 128;
#pragma unroll
        for (int nt = 0; nt < 8; nt++) {
            int col = wn + nt * 8 + t2;
            float v0 = acc[nt][half * 2 + 0] + bs[col];
            float v1 = acc[nt][half * 2 + 1] + bs[col + 1];
            *(float2*)(cp + col) = make_float2(v0, v1);
        }
    }
}

// ---------------- fused gather + GEMM (layers; K=128) -------------------------
// Phase 0: warp w gathers dst rows [w*8, w*8+8): A[r][:] = rin[r] * sum X[src]*rout[src],
//          splits to bf16 hi/lo directly into per-chunk ldmatrix layout.
// Phase 1: 4 K-chunks, A from smem planes, B (weights) double-buffered from gmem.
// Epilogue: maybe_relu(acc + bias); optional accum into C.
#define ACH 5184                     // chunk plane stride (80B rows, +64 bank stagger)
#define A_PLANE (4 * ACH)            // 20736
#define FB_BASE (2 * A_PLANE)        // 41472: two B buffers of 2*BBUF each
#define FB_BIAS (FB_BASE + 2 * (2 * BBUF))   // 74240
#define FUSED_SMEM (FB_BIAS + 512)

__global__ __launch_bounds__(256, 2) void fused_gemm_kernel(
    const float* __restrict__ X, const float* __restrict__ W,
    const float* __restrict__ bias,
    const float* __restrict__ rout, const float* __restrict__ rin,
    const int* __restrict__ off, const int* __restrict__ esrc,
    float* __restrict__ C, int doRelu, int accum)
{
    extern __shared__ char sm[];
    const uint32_t sbase = smem_u32(sm);
    const int tid = threadIdx.x, lane = tid & 31, wid = tid >> 5;
    const int blockRow = blockIdx.x * BMROWS;
    const int wm = (wid & 3) * 16;
    const int wn = (wid >> 2) * 64;

    if (tid < 128) ((float*)(sm + FB_BIAS))[tid] = bias[tid];

    // ---- phase 0: CSR gather into A planes (bf16 hi/lo, chunked layout) ----
    {
        const int chnk = lane >> 3;          // which 32-k chunk this lane's cols fall in
        const int q = lane & 7;              // 8B slot within chunk row
#pragma unroll
        for (int rr = 0; rr < 8; rr++) {
            int r = wid * 8 + rr;            // row in tile (0..63)
            int gr = blockRow + r;
            float4 a4 = make_float4(0.f, 0.f, 0.f, 0.f);
            if (gr < NN) {
                int b = __ldg(&off[gr]);
                int e = (gr + 1 < NN) ? __ldg(&off[gr + 1]) : NE;
                for (int j = b; j < e; j++) {
                    int s = __ldg(&esrc[j]);
                    float sc = __ldg(&rout[s]);
                    float4 xv = *(const float4*)(X + (size_t)s * H + lane * 4);
                    a4.x += xv.x * sc; a4.y += xv.y * sc;
                    a4.z += xv.z * sc; a4.w += xv.w * sc;
                }
                float ri = __ldg(&rin[gr]);
                a4.x *= ri; a4.y *= ri; a4.z *= ri; a4.w *= ri;
            }
            float rx, ry, rz, rw;
            uint2 hi, lo;
            split2(a4.x, a4.y, hi.x, rx, ry);
            split2(a4.z, a4.w, hi.y, rz, rw);
            lo.x = pack2(rx, ry);
            lo.y = pack2(rz, rw);
            uint32_t o = (uint32_t)chnk * ACH + (uint32_t)r * 80 + q * 8;
            *(uint2*)(sm + o) = hi;
            *(uint2*)(sm + A_PLANE + o) = lo;
        }
    }

    // B chunk loader (weights): 32 k-rows x 128 n, XOR chunk swizzle
    auto load_b = [&](int ch) {
        const int k0 = ch * 32;
        char* buf = sm + FB_BASE + (ch & 1) * (2 * BBUF);
#pragma unroll
        for (int i = 0; i < 4; i++) {
            int idx = tid + i * 256;
            int kk = idx >> 5, q = idx & 31;
            float4 v = *(const float4*)(W + (size_t)(k0 + kk) * 128 + q * 4);
            float rx, ry, rz, rw;
            uint2 hi, lo;
            split2(v.x, v.y, hi.x, rx, ry);
            split2(v.z, v.w, hi.y, rz, rw);
            lo.x = pack2(rx, ry);
            lo.y = pack2(rz, rw);
            uint32_t o = (uint32_t)kk * 256 + ((((uint32_t)(q >> 1)) ^ (kk & 7)) << 4) + (q & 1) * 8;
            *(uint2*)(buf + o) = hi;
            *(uint2*)(buf + BBUF + o) = lo;
        }
    };

    load_b(0);
    __syncthreads();

    float acc[8][4];
#pragma unroll
    for (int j = 0; j < 8; j++)
#pragma unroll
        for (int k = 0; k < 4; k++) acc[j][k] = 0.f;

    const int r8 = lane & 7, sel = lane >> 3;
    const int a_row = r8 + ((sel & 1) << 3);
    const int a_kb  = (sel >> 1) << 4;
    const int b_csel = sel >> 1;

#pragma unroll
    for (int ch = 0; ch < 4; ch++) {
        if (ch < 3) load_b(ch + 1);
        const uint32_t abase = sbase + ch * ACH;
        const uint32_t bbase = sbase + FB_BASE + (ch & 1) * (2 * BBUF);

#pragma unroll
        for (int h = 0; h < 2; h++) {
            uint32_t ah[4], al[4], bf[4][4];
            {
                uint32_t aaddr = abase + (wm + a_row) * 80 + h * 32 + a_kb;
                ldm_x4(ah, aaddr);
                ldm_x4(al, aaddr + A_PLANE);
            }
            const int kk = h * 16 + a_row;
            const uint32_t brow = bbase + (uint32_t)kk * 256;
#pragma unroll
            for (int j = 0; j < 4; j++) {
                uint32_t chunk = (uint32_t)((wn >> 3) + j * 2 + b_csel) ^ (kk & 7);
                ldm_x4_t(bf[j], brow + chunk * 16);
            }
#pragma unroll
            for (int j = 0; j < 4; j++) {
                mma_bf16(acc[2 * j],     ah, bf[j][0], bf[j][1]);
                mma_bf16(acc[2 * j + 1], ah, bf[j][2], bf[j][3]);
                mma_bf16(acc[2 * j],     al, bf[j][0], bf[j][1]);
                mma_bf16(acc[2 * j + 1], al, bf[j][2], bf[j][3]);
            }
#pragma unroll
            for (int j = 0; j < 4; j++) {
                uint32_t chunk = (uint32_t)((wn >> 3) + j * 2 + b_csel) ^ (kk & 7);
                ldm_x4_t(bf[j], brow + BBUF + chunk * 16);
            }
#pragma unroll
            for (int j = 0; j < 4; j++) {
                mma_bf16(acc[2 * j],     ah, bf[j][0], bf[j][1]);
                mma_bf16(acc[2 * j + 1], ah, bf[j][2], bf[j][3]);
            }
        }
        __syncthreads();
    }

    // epilogue: relu?(acc + bias), optional accumulate
    const float* bs = (const float*)(sm + FB_BIAS);
    const int g = lane >> 2;
    const int t2 = (lane & 3) * 2;
#pragma unroll
    for (int half = 0; half < 2; half++) {
        int row = blockRow + wm + g + half * 8;
        if (row >= NN) continue;
        float* cp = C + (size_t)row * 128;
#pragma unroll
        for (int nt = 0; nt < 8; nt++) {
            int col = wn + nt * 8 + t2;
            float v0 = acc[nt][half * 2 + 0] + bs[col];
            float v1 = acc[nt][half * 2 + 1] + bs[col + 1];
            if (doRelu) { v0 = fmaxf(v0, 0.f); v1 = fmaxf(v1, 0.f); }
            if (accum) {
                float2 o = *(const float2*)(cp + col);
                v0 += o.x; v1 += o.y;
            }
            *(float2*)(cp + col) = make_float2(v0, v1);
        }
    }
}

// ---------------- host orchestration -----------------------------------------
extern "C" void kernel_launch(void* const* d_in, const int* in_sizes, int n_in,
                              void* d_out, int out_size) {
    const float* feat_user = (const float*)d_in[0];
    const float* feat_item = (const float*)d_in[1];
    const int* src_uu = (const int*)d_in[2];
    const int* dst_uu = (const int*)d_in[3];
    const int* src_ui = (const int*)d_in[4];
    const int* dst_ui = (const int*)d_in[5];
    const int* src_iu = (const int*)d_in[6];
    const int* dst_iu = (const int*)d_in[7];
    const float* We_u = (const float*)d_in[8];
    const float* be_u = (const float*)d_in[9];
    const float* We_i = (const float*)d_in[10];
    const float* be_i = (const float*)d_in[11];
    const float* W[3][3];
    const float* B[3][3];
    for (int l = 0; l < 3; l++)
        for (int e = 0; e < 3; e++) {
            W[l][e] = (const float*)d_in[12 + l * 6 + e * 2];
            B[l][e] = (const float*)d_in[12 + l * 6 + e * 2 + 1];
        }

    float *hu, *hi, *deg;
    int *degi, *off, *cur, *esrc, *bsum;
    cudaGetSymbolAddress((void**)&hu, g_hu);
    cudaGetSymbolAddress((void**)&hi, g_hi);
    cudaGetSymbolAddress((void**)&deg, g_deg);
    cudaGetSymbolAddress((void**)&degi, g_degi);
    cudaGetSymbolAddress((void**)&off, g_off);
    cudaGetSymbolAddress((void**)&cur, g_cur);
    cudaGetSymbolAddress((void**)&esrc, g_esrc);
    cudaGetSymbolAddress((void**)&bsum, g_bsum);
    float* out = (float*)d_out;

    cudaFuncSetAttribute(mma_gemm_kernel,
                         cudaFuncAttributeMaxDynamicSharedMemorySize, TCSMEM);
    cudaFuncSetAttribute(fused_gemm_kernel,
                         cudaFuncAttributeMaxDynamicSharedMemorySize, FUSED_SMEM);

    // ---- degree + CSR build ----
    zero_int_kernel<<<256, 256>>>(degi, 6 * NN);
    zero_int_kernel<<<256, 256>>>(cur, 3 * NN);
    deg_count_kernel<<<(NE + 255) / 256, 256>>>(src_uu, dst_uu, src_ui, dst_ui,
                                                src_iu, dst_iu, degi);
    deg_finalize_kernel<<<(NN + 255) / 256, 256>>>(degi, deg);
    {
        dim3 g1(SCAN_NB, 3);
        scan_s1<<<g1, 256>>>(degi, off, bsum);
        scan_s2<<<1, 32>>>(bsum);
        dim3 g3((NN + 255) / 256, 3);
        scan_s3<<<g3, 256>>>(off, bsum);
    }
    fill_kernel<<<(NE + 255) / 256, 256>>>(src_uu, dst_uu, off + 0 * NN, cur + 0 * NN, esrc + 0 * NE);
    fill_kernel<<<(NE + 255) / 256, 256>>>(src_ui, dst_ui, off + 1 * NN, cur + 1 * NN, esrc + 1 * NE);
    fill_kernel<<<(NE + 255) / 256, 256>>>(src_iu, dst_iu, off + 2 * NN, cur + 2 * NN, esrc + 2 * NE);

    const float* rout_uu = deg + 0 * NN;
    const float* rin_uu  = deg + 1 * NN;
    const float* rout_ui = deg + 2 * NN;
    const float* rin_ui  = deg + 3 * NN;
    const float* rout_iu = deg + 4 * NN;
    const float* rin_iu  = deg + 5 * NN;

    int grid = (NN + BMROWS - 1) / BMROWS;

    // ---- embed (dense GEMM) ----
    mma_gemm_kernel<<<grid, 256, TCSMEM>>>(feat_user, We_u, be_u, hu, NN, D_U);
    mma_gemm_kernel<<<grid, 256, TCSMEM>>>(feat_item, We_i, be_i, hi, NN, D_I);

    // ---- layers: fused gather+GEMM ----
    int cur_pp = 0;
    for (int l = 0; l < 3; l++) {
        int relu = (l < 2) ? 1 : 0;
        float* hu_cur = hu + (size_t)cur_pp * NUH;
        float* hi_cur = hi + (size_t)cur_pp * NUH;
        float* hu_nxt = (l == 2) ? out : hu + (size_t)(1 - cur_pp) * NUH;
        float* hi_nxt = (l == 2) ? out + (size_t)NUH : hi + (size_t)(1 - cur_pp) * NUH;

        // hu_nxt = relu?( (rin_uu * agg_uu(hu)) @ W_uu + b_uu )
        //        + relu?( (rin_iu * agg_iu(hi)) @ W_iu + b_iu )
        fused_gemm_kernel<<<grid, 256, FUSED_SMEM>>>(hu_cur, W[l][0], B[l][0],
                                                     rout_uu, rin_uu,
                                                     off + 0 * NN, esrc + 0 * NE,
                                                     hu_nxt, relu, 0);
        fused_gemm_kernel<<<grid, 256, FUSED_SMEM>>>(hi_cur, W[l][2], B[l][2],
                                                     rout_iu, rin_iu,
                                                     off + 2 * NN, esrc + 2 * NE,
                                                     hu_nxt, relu, 1);
        // hi_nxt = relu?( (rin_ui * agg_ui(hu)) @ W_ui + b_ui )
        fused_gemm_kernel<<<grid, 256, FUSED_SMEM>>>(hu_cur, W[l][1], B[l][1],
                                                     rout_ui, rin_ui,
                                                     off + 1 * NN, esrc + 1 * NE,
                                                     hi_nxt, relu, 0);
        cur_pp ^= 1;
    }
    (void)in_sizes; (void)n_in; (void)out_size;
}

// round 13
// speedup vs baseline: 1.2127x; 1.2127x over previous
#include <cuda_runtime.h>
#include <cuda_bf16.h>
#include <cstdint>

#define NN  100000
#define NE  500000
#define H   128
#define D_U 256
#define D_I 300
#define NUH (NN * H)
#define SCAN_NB 98            // ceil(NN/1024)

// ---------------- scratch (static device globals; no allocation) -------------
__device__ float g_hu[2][NUH];
__device__ float g_hi[2][NUH];
__device__ float g_S[3][NUH];      // gathered+rin-scaled: 0=uu, 1=ui, 2=iu
__device__ float g_deg[6][NN];     // rsqrt: 0 out_uu, 1 in_uu, 2 out_ui, 3 in_ui, 4 out_iu, 5 in_iu
__device__ int   g_degi[6][NN];
__device__ int   g_off[3][NN];     // CSR row starts per etype: 0=uu, 1=ui, 2=iu
__device__ int   g_cur[3][NN];
__device__ int   g_esrc[3][NE];    // edge src sorted by dst
__device__ int   g_bsum[3][128];

// ---------------- small helpers ----------------------------------------------
__device__ __forceinline__ uint32_t smem_u32(const void* p) {
    uint32_t a;
    asm("{ .reg .u64 t; cvta.to.shared.u64 t, %1; cvt.u32.u64 %0, t; }" : "=r"(a) : "l"(p));
    return a;
}
__device__ __forceinline__ void ldm_x4(uint32_t* r, uint32_t addr) {
    asm volatile("ldmatrix.sync.aligned.m8n8.x4.shared.b16 {%0,%1,%2,%3}, [%4];"
                 : "=r"(r[0]), "=r"(r[1]), "=r"(r[2]), "=r"(r[3]) : "r"(addr));
}
__device__ __forceinline__ void ldm_x4_t(uint32_t* r, uint32_t addr) {
    asm volatile("ldmatrix.sync.aligned.m8n8.x4.trans.shared.b16 {%0,%1,%2,%3}, [%4];"
                 : "=r"(r[0]), "=r"(r[1]), "=r"(r[2]), "=r"(r[3]) : "r"(addr));
}
__device__ __forceinline__ void mma_bf16(float* d, const uint32_t* a, uint32_t b0, uint32_t b1) {
    asm volatile("mma.sync.aligned.m16n8k16.row.col.f32.bf16.bf16.f32 "
                 "{%0,%1,%2,%3}, {%4,%5,%6,%7}, {%8,%9}, {%0,%1,%2,%3};"
                 : "+f"(d[0]), "+f"(d[1]), "+f"(d[2]), "+f"(d[3])
                 : "r"(a[0]), "r"(a[1]), "r"(a[2]), "r"(a[3]), "r"(b0), "r"(b1));
}
__device__ __forceinline__ void split2(float a, float b, uint32_t& hi, float& ra, float& rb) {
    __nv_bfloat16 ha = __float2bfloat16(a), hb = __float2bfloat16(b);
    hi = (uint32_t)__bfloat16_as_ushort(ha) | ((uint32_t)__bfloat16_as_ushort(hb) << 16);
    ra = a - __bfloat162float(ha);
    rb = b - __bfloat162float(hb);
}
__device__ __forceinline__ uint32_t pack2(float a, float b) {
    return (uint32_t)__bfloat16_as_ushort(__float2bfloat16(a)) |
           ((uint32_t)__bfloat16_as_ushort(__float2bfloat16(b)) << 16);
}

// ---------------- setup kernels ----------------------------------------------
__global__ void zero_int_kernel(int* p, int n) {
    int i = blockIdx.x * blockDim.x + threadIdx.x;
    int stride = gridDim.x * blockDim.x;
    for (; i < n; i += stride) p[i] = 0;
}

__global__ void deg_count_kernel(const int* __restrict__ suu, const int* __restrict__ duu,
                                 const int* __restrict__ sui, const int* __restrict__ dui,
                                 const int* __restrict__ siu, const int* __restrict__ diu,
                                 int* __restrict__ degi) {
    int i = blockIdx.x * blockDim.x + threadIdx.x;
    if (i >= NE) return;
    atomicAdd(&degi[0 * NN + suu[i]], 1);
    atomicAdd(&degi[1 * NN + duu[i]], 1);
    atomicAdd(&degi[2 * NN + sui[i]], 1);
    atomicAdd(&degi[3 * NN + dui[i]], 1);
    atomicAdd(&degi[4 * NN + siu[i]], 1);
    atomicAdd(&degi[5 * NN + diu[i]], 1);
}

__global__ void deg_finalize_kernel(const int* __restrict__ degi, float* __restrict__ deg) {
    int i = blockIdx.x * blockDim.x + threadIdx.x;
    if (i >= NN) return;
#pragma unroll
    for (int j = 0; j < 6; j++)
        deg[j * NN + i] = rsqrtf(fmaxf((float)degi[j * NN + i], 1.f));
}

__global__ void scan_s1(const int* __restrict__ degi, int* __restrict__ off,
                        int* __restrict__ bsum) {
    int et = blockIdx.y;
    const int* d = degi + (1 + 2 * et) * NN;
    int* o = off + et * NN;
    __shared__ int wsum[8], woff[8];
    int t = threadIdx.x;
    int base = blockIdx.x * 1024 + t * 4;
    int x[4];
#pragma unroll
    for (int j = 0; j < 4; j++) x[j] = (base + j < NN) ? d[base + j] : 0;
    int tl = x[0] + x[1] + x[2] + x[3];
    int incl = tl;
#pragma unroll
    for (int s = 1; s < 32; s <<= 1) {
        int y = __shfl_up_sync(0xffffffff, incl, s);
        if ((t & 31) >= s) incl += y;
    }
    if ((t & 31) == 31) wsum[t >> 5] = incl;
    __syncthreads();
    if (t == 0) {
        int a = 0;
#pragma unroll
        for (int k = 0; k < 8; k++) { woff[k] = a; a += wsum[k]; }
    }
    __syncthreads();
    int run = woff[t >> 5] + incl - tl;
#pragma unroll
    for (int j = 0; j < 4; j++) {
        if (base + j < NN) o[base + j] = run;
        run += x[j];
    }
    if (t == 255) bsum[et * 128 + blockIdx.x] = woff[7] + wsum[7];
}

__global__ void scan_s2(int* bsum) {
    int et = threadIdx.x;
    if (et < 3) {
        int a = 0;
        for (int i = 0; i < SCAN_NB; i++) {
            int t = bsum[et * 128 + i];
            bsum[et * 128 + i] = a;
            a += t;
        }
    }
}

__global__ void scan_s3(int* __restrict__ off, const int* __restrict__ bsum) {
    int et = blockIdx.y;
    int i = blockIdx.x * blockDim.x + threadIdx.x;
    if (i < NN) off[et * NN + i] += bsum[et * 128 + (i >> 10)];
}

__global__ void fill_kernel(const int* __restrict__ src, const int* __restrict__ dst,
                            const int* __restrict__ off, int* __restrict__ cur,
                            int* __restrict__ esrc) {
    int e = blockIdx.x * blockDim.x + threadIdx.x;
    if (e >= NE) return;
    int d = dst[e];
    int p = atomicAdd(&cur[d], 1);
    esrc[off[d] + p] = src[e];
}

// ---------------- 3-etype CSR gather (one launch per layer) -------------------
// blockIdx.y = etype (0=uu from Xu, 1=ui from Xu, 2=iu from Xi)
// S[r] = rin[r] * sum_edges X[src]*rout[src]
__global__ __launch_bounds__(256) void gather3_kernel(
    const float* __restrict__ Xu, const float* __restrict__ Xi,
    const float* __restrict__ deg,
    const int* __restrict__ off, const int* __restrict__ esrc,
    float* __restrict__ S) {
    int et = blockIdx.y;
    const float* X = (et == 2) ? Xi : Xu;
    const float* rout;
    const float* rin;
    if (et == 0)      { rout = deg + 0 * NN; rin = deg + 1 * NN; }
    else if (et == 1) { rout = deg + 2 * NN; rin = deg + 3 * NN; }
    else              { rout = deg + 4 * NN; rin = deg + 5 * NN; }
    const int* o = off + et * NN;
    const int* es = esrc + (size_t)et * NE;
    float* Sout = S + (size_t)et * NUH;

    int r = blockIdx.x * 8 + (threadIdx.x >> 5);
    if (r >= NN) return;
    int lane = threadIdx.x & 31;
    int b = __ldg(&o[r]);
    int e = (r + 1 < NN) ? __ldg(&o[r + 1]) : NE;
    float4 acc = make_float4(0.f, 0.f, 0.f, 0.f);
    for (int j = b; j < e; j++) {
        int s = __ldg(&es[j]);
        float rr = __ldg(&rout[s]);
        float4 xv = *(const float4*)(X + (size_t)s * H + lane * 4);
        acc.x += xv.x * rr; acc.y += xv.y * rr;
        acc.z += xv.z * rr; acc.w += xv.w * rr;
    }
    float ri = __ldg(&rin[r]);
    acc.x *= ri; acc.y *= ri; acc.z *= ri; acc.w *= ri;
    *(float4*)(Sout + (size_t)r * H + lane * 4) = acc;
}

// ---------------- shared GEMM tile config ------------------------------------
#define BMROWS 64
#define ABUF 5120                  // 64 rows * 80B
#define BBUF 8192                  // 32 k-rows * 256B
#define BUFSZ (2 * ABUF + 2 * BBUF)
#define SM_BIAS (2 * BUFSZ)
#define TCSMEM (SM_BIAS + 1024)

// ---------------- dense bf16x3 GEMM (embeds; any K) ---------------------------
__global__ __launch_bounds__(256, 3) void mma_gemm_kernel(
    const float* __restrict__ A, const float* __restrict__ W,
    const float* __restrict__ bias,
    float* __restrict__ C, int M, int K)
{
    extern __shared__ char sm[];
    const uint32_t sbase = smem_u32(sm);
    const int tid = threadIdx.x, lane = tid & 31, wid = tid >> 5;
    const int blockRow = blockIdx.x * BMROWS;
    const int wm = (wid & 3) * 16;
    const int wn = (wid >> 2) * 64;

    if (tid < 128) ((float*)(sm + SM_BIAS))[tid] = bias[tid];

    float acc[8][4];
#pragma unroll
    for (int j = 0; j < 8; j++)
#pragma unroll
        for (int k = 0; k < 4; k++) acc[j][k] = 0.f;

    const int nch = (K + 31) / 32;

    const int r8 = lane & 7, sel = lane >> 3;
    const int a_row = r8 + ((sel & 1) << 3);
    const int a_kb  = (sel >> 1) << 4;
    const int b_csel = sel >> 1;

    auto load_chunk = [&](int ch) {
        const int k0 = ch * 32;
        char* buf = sm + (ch & 1) * BUFSZ;
#pragma unroll
        for (int i = 0; i < 2; i++) {
            int idx = tid + i * 256;
            int row = idx >> 3, q = idx & 7;
            int gm = blockRow + row, gk = k0 + q * 4;
            float4 v = make_float4(0.f, 0.f, 0.f, 0.f);
            if (gm < M) {
                const float* ap = A + (size_t)gm * K + gk;
                if (gk + 3 < K) v = *(const float4*)ap;
                else {
                    if (gk + 0 < K) v.x = ap[0];
                    if (gk + 1 < K) v.y = ap[1];
                    if (gk + 2 < K) v.z = ap[2];
                    if (gk + 3 < K) v.w = ap[3];
                }
            }
            float rx, ry, rz, rw;
            uint2 hi, lo;
            split2(v.x, v.y, hi.x, rx, ry);
            split2(v.z, v.w, hi.y, rz, rw);
            lo.x = pack2(rx, ry);
            lo.y = pack2(rz, rw);
            *(uint2*)(buf + (size_t)row * 80 + q * 8) = hi;
            *(uint2*)(buf + ABUF + (size_t)row * 80 + q * 8) = lo;
        }
#pragma unroll
        for (int i = 0; i < 4; i++) {
            int idx = tid + i * 256;
            int kk = idx >> 5, q = idx & 31;
            int gk = k0 + kk;
            float4 v = make_float4(0.f, 0.f, 0.f, 0.f);
            if (gk < K) v = *(const float4*)(W + (size_t)gk * 128 + q * 4);
            float rx, ry, rz, rw;
            uint2 hi, lo;
            split2(v.x, v.y, hi.x, rx, ry);
            split2(v.z, v.w, hi.y, rz, rw);
            lo.x = pack2(rx, ry);
            lo.y = pack2(rz, rw);
            uint32_t o = (uint32_t)kk * 256 + ((((uint32_t)(q >> 1)) ^ (kk & 7)) << 4) + (q & 1) * 8;
            *(uint2*)(buf + 2 * ABUF + o) = hi;
            *(uint2*)(buf + 2 * ABUF + BBUF + o) = lo;
        }
    };

    load_chunk(0);
    __syncthreads();

    for (int ch = 0; ch < nch; ch++) {
        if (ch + 1 < nch) load_chunk(ch + 1);
        const uint32_t bufb = sbase + (ch & 1) * BUFSZ;

#pragma unroll
        for (int h = 0; h < 2; h++) {
            uint32_t ah[4], al[4], bf[4][4];
            {
                uint32_t aaddr = bufb + (wm + a_row) * 80 + h * 32 + a_kb;
                ldm_x4(ah, aaddr);
                ldm_x4(al, aaddr + ABUF);
            }
            const int kk = h * 16 + a_row;
            const uint32_t brow = bufb + 2 * ABUF + (uint32_t)kk * 256;
#pragma unroll
            for (int j = 0; j < 4; j++) {
                uint32_t chunk = (uint32_t)((wn >> 3) + j * 2 + b_csel) ^ (kk & 7);
                ldm_x4_t(bf[j], brow + chunk * 16);
            }
#pragma unroll
            for (int j = 0; j < 4; j++) {
                mma_bf16(acc[2 * j],     ah, bf[j][0], bf[j][1]);
                mma_bf16(acc[2 * j + 1], ah, bf[j][2], bf[j][3]);
                mma_bf16(acc[2 * j],     al, bf[j][0], bf[j][1]);
                mma_bf16(acc[2 * j + 1], al, bf[j][2], bf[j][3]);
            }
#pragma unroll
            for (int j = 0; j < 4; j++) {
                uint32_t chunk = (uint32_t)((wn >> 3) + j * 2 + b_csel) ^ (kk & 7);
                ldm_x4_t(bf[j], brow + BBUF + chunk * 16);
            }
#pragma unroll
            for (int j = 0; j < 4; j++) {
                mma_bf16(acc[2 * j],     ah, bf[j][0], bf[j][1]);
                mma_bf16(acc[2 * j + 1], ah, bf[j][2], bf[j][3]);
            }
        }
        __syncthreads();
    }

    const float* bs = (const float*)(sm + SM_BIAS);
    const int g = lane >> 2;
    const int t2 = (lane & 3) * 2;
#pragma unroll
    for (int half = 0; half < 2; half++) {
        int row = blockRow + wm + g + half * 8;
        if (row >= M) continue;
        float* cp = C + (size_t)row * 128;
#pragma unroll
        for (int nt = 0; nt < 8; nt++) {
            int col = wn + nt * 8 + t2;
            float v0 = acc[nt][half * 2 + 0] + bs[col];
            float v1 = acc[nt][half * 2 + 1] + bs[col + 1];
            *(float2*)(cp + col) = make_float2(v0, v1);
        }
    }
}

// ---------------- layer GEMM: one launch, grid.y picks output -----------------
// y==0: Cu = relu?(Suu@Wuu+buu) + relu?(Siu@Wiu+biu)   (dual-term, K=128 each)
// y==1: Ci = relu?(Sui@Wui+bui)
__global__ __launch_bounds__(256, 2) void layer_gemm_kernel(
    const float* __restrict__ Suu, const float* __restrict__ Wuu, const float* __restrict__ buu,
    const float* __restrict__ Siu, const float* __restrict__ Wiu, const float* __restrict__ biu,
    const float* __restrict__ Sui, const float* __restrict__ Wui, const float* __restrict__ bui,
    float* __restrict__ Cu, float* __restrict__ Ci, int doRelu)
{
    extern __shared__ char sm[];
    const uint32_t sbase = smem_u32(sm);
    const int tid = threadIdx.x, lane = tid & 31, wid = tid >> 5;
    const int blockRow = blockIdx.x * BMROWS;
    const int wm = (wid & 3) * 16;
    const int wn = (wid >> 2) * 64;

    const float* Asrc[2];
    const float* Wsrc[2];
    float* C;
    int nterm;
    if (blockIdx.y == 0) {
        Asrc[0] = Suu; Wsrc[0] = Wuu;
        Asrc[1] = Siu; Wsrc[1] = Wiu;
        C = Cu; nterm = 2;
        if (tid < 128) {
            ((float*)(sm + SM_BIAS))[tid] = buu[tid];
            ((float*)(sm + SM_BIAS + 512))[tid] = biu[tid];
        }
    } else {
        Asrc[0] = Sui; Wsrc[0] = Wui;
        Asrc[1] = Sui; Wsrc[1] = Wui;
        C = Ci; nterm = 1;
        if (tid < 128) ((float*)(sm + SM_BIAS))[tid] = bui[tid];
    }

    float acc[8][4], out[8][4];
#pragma unroll
    for (int j = 0; j < 8; j++)
#pragma unroll
        for (int k = 0; k < 4; k++) { acc[j][k] = 0.f; out[j][k] = 0.f; }

    const int r8 = lane & 7, sel = lane >> 3;
    const int a_row = r8 + ((sel & 1) << 3);
    const int a_kb  = (sel >> 1) << 4;
    const int b_csel = sel >> 1;
    const int g = lane >> 2;
    const int t2 = (lane & 3) * 2;

    // chunk index ci in [0, 4*nterm): term = ci>>2, k0 = (ci&3)*32; K=128 fixed
    auto load_chunk = [&](int ci) {
        const int term = ci >> 2;
        const int k0 = (ci & 3) * 32;
        const float* A = Asrc[term];
        const float* W = Wsrc[term];
        char* buf = sm + (ci & 1) * BUFSZ;
#pragma unroll
        for (int i = 0; i < 2; i++) {
            int idx = tid + i * 256;
            int row = idx >> 3, q = idx & 7;
            int gm = blockRow + row;
            float4 v = make_float4(0.f, 0.f, 0.f, 0.f);
            if (gm < NN) v = *(const float4*)(A + (size_t)gm * H + k0 + q * 4);
            float rx, ry, rz, rw;
            uint2 hi, lo;
            split2(v.x, v.y, hi.x, rx, ry);
            split2(v.z, v.w, hi.y, rz, rw);
            lo.x = pack2(rx, ry);
            lo.y = pack2(rz, rw);
            *(uint2*)(buf + (size_t)row * 80 + q * 8) = hi;
            *(uint2*)(buf + ABUF + (size_t)row * 80 + q * 8) = lo;
        }
#pragma unroll
        for (int i = 0; i < 4; i++) {
            int idx = tid + i * 256;
            int kk = idx >> 5, q = idx & 31;
            float4 v = *(const float4*)(W + (size_t)(k0 + kk) * 128 + q * 4);
            float rx, ry, rz, rw;
            uint2 hi, lo;
            split2(v.x, v.y, hi.x, rx, ry);
            split2(v.z, v.w, hi.y, rz, rw);
            lo.x = pack2(rx, ry);
            lo.y = pack2(rz, rw);
            uint32_t o = (uint32_t)kk * 256 + ((((uint32_t)(q >> 1)) ^ (kk & 7)) << 4) + (q & 1) * 8;
            *(uint2*)(buf + 2 * ABUF + o) = hi;
            *(uint2*)(buf + 2 * ABUF + BBUF + o) = lo;
        }
    };

    const int total = nterm * 4;
    load_chunk(0);
    __syncthreads();

    for (int ci = 0; ci < total; ci++) {
        if (ci + 1 < total) load_chunk(ci + 1);
        const uint32_t bufb = sbase + (ci & 1) * BUFSZ;

#pragma unroll
        for (int h = 0; h < 2; h++) {
            uint32_t ah[4], al[4], bf[4][4];
            {
                uint32_t aaddr = bufb + (wm + a_row) * 80 + h * 32 + a_kb;
                ldm_x4(ah, aaddr);
                ldm_x4(al, aaddr + ABUF);
            }
            const int kk = h * 16 + a_row;
            const uint32_t brow = bufb + 2 * ABUF + (uint32_t)kk * 256;
#pragma unroll
            for (int j = 0; j < 4; j++) {
                uint32_t chunk = (uint32_t)((wn >> 3) + j * 2 + b_csel) ^ (kk & 7);
                ldm_x4_t(bf[j], brow + chunk * 16);
            }
#pragma unroll
            for (int j = 0; j < 4; j++) {
                mma_bf16(acc[2 * j],     ah, bf[j][0], bf[j][1]);
                mma_bf16(acc[2 * j + 1], ah, bf[j][2], bf[j][3]);
                mma_bf16(acc[2 * j],     al, bf[j][0], bf[j][1]);
                mma_bf16(acc[2 * j + 1], al, bf[j][2], bf[j][3]);
            }
#pragma unroll
            for (int j = 0; j < 4; j++) {
                uint32_t chunk = (uint32_t)((wn >> 3) + j * 2 + b_csel) ^ (kk & 7);
                ldm_x4_t(bf[j], brow + BBUF + chunk * 16);
            }
#pragma unroll
            for (int j = 0; j < 4; j++) {
                mma_bf16(acc[2 * j],     ah, bf[j][0], bf[j][1]);
                mma_bf16(acc[2 * j + 1], ah, bf[j][2], bf[j][3]);
            }
        }
        __syncthreads();

        if ((ci & 3) == 3) {
            // fold this term: out += maybe_relu(acc + bias[term]); reset acc
            const float* bt = (const float*)(sm + SM_BIAS + (ci >> 2) * 512);
#pragma unroll
            for (int nt = 0; nt < 8; nt++)
#pragma unroll
                for (int half = 0; half < 2; half++)
#pragma unroll
                    for (int j2 = 0; j2 < 2; j2++) {
                        int col = wn + nt * 8 + t2 + j2;
                        float v = acc[nt][half * 2 + j2] + bt[col];
                        if (doRelu) v = fmaxf(v, 0.f);
                        out[nt][half * 2 + j2] += v;
                        acc[nt][half * 2 + j2] = 0.f;
                    }
        }
    }

    // epilogue: write out
#pragma unroll
    for (int half = 0; half < 2; half++) {
        int row = blockRow + wm + g + half * 8;
        if (row >= NN) continue;
        float* cp = C + (size_t)row * 128;
#pragma unroll
        for (int nt = 0; nt < 8; nt++) {
            int col = wn + nt * 8 + t2;
            *(float2*)(cp + col) = make_float2(out[nt][half * 2 + 0],
                                               out[nt][half * 2 + 1]);
        }
    }
}

// ---------------- host orchestration -----------------------------------------
extern "C" void kernel_launch(void* const* d_in, const int* in_sizes, int n_in,
                              void* d_out, int out_size) {
    const float* feat_user = (const float*)d_in[0];
    const float* feat_item = (const float*)d_in[1];
    const int* src_uu = (const int*)d_in[2];
    const int* dst_uu = (const int*)d_in[3];
    const int* src_ui = (const int*)d_in[4];
    const int* dst_ui = (const int*)d_in[5];
    const int* src_iu = (const int*)d_in[6];
    const int* dst_iu = (const int*)d_in[7];
    const float* We_u = (const float*)d_in[8];
    const float* be_u = (const float*)d_in[9];
    const float* We_i = (const float*)d_in[10];
    const float* be_i = (const float*)d_in[11];
    const float* W[3][3];
    const float* B[3][3];
    for (int l = 0; l < 3; l++)
        for (int e = 0; e < 3; e++) {
            W[l][e] = (const float*)d_in[12 + l * 6 + e * 2];
            B[l][e] = (const float*)d_in[12 + l * 6 + e * 2 + 1];
        }

    float *hu, *hi, *S, *deg;
    int *degi, *off, *cur, *esrc, *bsum;
    cudaGetSymbolAddress((void**)&hu, g_hu);
    cudaGetSymbolAddress((void**)&hi, g_hi);
    cudaGetSymbolAddress((void**)&S, g_S);
    cudaGetSymbolAddress((void**)&deg, g_deg);
    cudaGetSymbolAddress((void**)&degi, g_degi);
    cudaGetSymbolAddress((void**)&off, g_off);
    cudaGetSymbolAddress((void**)&cur, g_cur);
    cudaGetSymbolAddress((void**)&esrc, g_esrc);
    cudaGetSymbolAddress((void**)&bsum, g_bsum);
    float* out = (float*)d_out;

    cudaFuncSetAttribute(mma_gemm_kernel,
                         cudaFuncAttributeMaxDynamicSharedMemorySize, TCSMEM);
    cudaFuncSetAttribute(layer_gemm_kernel,
                         cudaFuncAttributeMaxDynamicSharedMemorySize, TCSMEM);

    // ---- degree + CSR build ----
    zero_int_kernel<<<256, 256>>>(degi, 6 * NN);
    zero_int_kernel<<<256, 256>>>(cur, 3 * NN);
    deg_count_kernel<<<(NE + 255) / 256, 256>>>(src_uu, dst_uu, src_ui, dst_ui,
                                                src_iu, dst_iu, degi);
    deg_finalize_kernel<<<(NN + 255) / 256, 256>>>(degi, deg);
    {
        dim3 g1(SCAN_NB, 3);
        scan_s1<<<g1, 256>>>(degi, off, bsum);
        scan_s2<<<1, 32>>>(bsum);
        dim3 g3((NN + 255) / 256, 3);
        scan_s3<<<g3, 256>>>(off, bsum);
    }
    fill_kernel<<<(NE + 255) / 256, 256>>>(src_uu, dst_uu, off + 0 * NN, cur + 0 * NN, esrc + 0 * NE);
    fill_kernel<<<(NE + 255) / 256, 256>>>(src_ui, dst_ui, off + 1 * NN, cur + 1 * NN, esrc + 1 * NE);
    fill_kernel<<<(NE + 255) / 256, 256>>>(src_iu, dst_iu, off + 2 * NN, cur + 2 * NN, esrc + 2 * NE);

    int grid = (NN + BMROWS - 1) / BMROWS;

    // ---- embed (dense GEMM) ----
    mma_gemm_kernel<<<grid, 256, TCSMEM>>>(feat_user, We_u, be_u, hu, NN, D_U);
    mma_gemm_kernel<<<grid, 256, TCSMEM>>>(feat_item, We_i, be_i, hi, NN, D_I);

    // ---- layers: 1 gather launch + 1 GEMM launch each ----
    float* Suu = S + 0 * (size_t)NUH;
    float* Sui = S + 1 * (size_t)NUH;
    float* Siu = S + 2 * (size_t)NUH;
    int cur_pp = 0;
    for (int l = 0; l < 3; l++) {
        int relu = (l < 2) ? 1 : 0;
        float* hu_cur = hu + (size_t)cur_pp * NUH;
        float* hi_cur = hi + (size_t)cur_pp * NUH;
        float* hu_nxt = (l == 2) ? out : hu + (size_t)(1 - cur_pp) * NUH;
        float* hi_nxt = (l == 2) ? out + (size_t)NUH : hi + (size_t)(1 - cur_pp) * NUH;

        dim3 gg((NN + 7) / 8, 3);
        gather3_kernel<<<gg, 256>>>(hu_cur, hi_cur, deg, off, esrc, S);

        dim3 lg(grid, 2);
        layer_gemm_kernel<<<lg, 256, TCSMEM>>>(Suu, W[l][0], B[l][0],
                                               Siu, W[l][2], B[l][2],
                                               Sui, W[l][1], B[l][1],
                                               hu_nxt, hi_nxt, relu);
        cur_pp ^= 1;
    }
    (void)in_sizes; (void)n_in; (void)out_size;
}

// round 14
// speedup vs baseline: 1.3145x; 1.0839x over previous
#include <cuda_runtime.h>
#include <cuda_bf16.h>
#include <cstdint>

#define NN  100000
#define NE  500000
#define H   128
#define D_U 256
#define D_I 300
#define NUH (NN * H)
#define NP  (NN * 64)         // uint32 pairs per S plane
#define SCAN_NB 98            // ceil(NN/1024)

// ---------------- scratch (static device globals; no allocation) -------------
__device__ float    g_hu[2][NUH];
__device__ float    g_hi[2][NUH];
__device__ uint32_t g_Sh[3][NP];   // gathered rows, bf16-hi pairs: 0=uu, 1=ui, 2=iu
__device__ uint32_t g_Sl[3][NP];   // bf16-lo pairs
__device__ uint32_t g_Wh[9][128 * 64]; // layer weights pre-split (idx = l*3+e)
__device__ uint32_t g_Wl[9][128 * 64];
__device__ float    g_deg[6][NN];  // rsqrt: 0 out_uu, 1 in_uu, 2 out_ui, 3 in_ui, 4 out_iu, 5 in_iu
__device__ int      g_degi[6][NN];
__device__ int      g_off[3][NN];
__device__ int      g_cur[3][NN];
__device__ int      g_esrc[3][NE];
__device__ int      g_bsum[3][128];

// ---------------- small helpers ----------------------------------------------
__device__ __forceinline__ uint32_t smem_u32(const void* p) {
    uint32_t a;
    asm("{ .reg .u64 t; cvta.to.shared.u64 t, %1; cvt.u32.u64 %0, t; }" : "=r"(a) : "l"(p));
    return a;
}
__device__ __forceinline__ void ldm_x4(uint32_t* r, uint32_t addr) {
    asm volatile("ldmatrix.sync.aligned.m8n8.x4.shared.b16 {%0,%1,%2,%3}, [%4];"
                 : "=r"(r[0]), "=r"(r[1]), "=r"(r[2]), "=r"(r[3]) : "r"(addr));
}
__device__ __forceinline__ void ldm_x4_t(uint32_t* r, uint32_t addr) {
    asm volatile("ldmatrix.sync.aligned.m8n8.x4.trans.shared.b16 {%0,%1,%2,%3}, [%4];"
                 : "=r"(r[0]), "=r"(r[1]), "=r"(r[2]), "=r"(r[3]) : "r"(addr));
}
__device__ __forceinline__ void mma_bf16(float* d, const uint32_t* a, uint32_t b0, uint32_t b1) {
    asm volatile("mma.sync.aligned.m16n8k16.row.col.f32.bf16.bf16.f32 "
                 "{%0,%1,%2,%3}, {%4,%5,%6,%7}, {%8,%9}, {%0,%1,%2,%3};"
                 : "+f"(d[0]), "+f"(d[1]), "+f"(d[2]), "+f"(d[3])
                 : "r"(a[0]), "r"(a[1]), "r"(a[2]), "r"(a[3]), "r"(b0), "r"(b1));
}
__device__ __forceinline__ void split2(float a, float b, uint32_t& hi, float& ra, float& rb) {
    __nv_bfloat16 ha = __float2bfloat16(a), hb = __float2bfloat16(b);
    hi = (uint32_t)__bfloat16_as_ushort(ha) | ((uint32_t)__bfloat16_as_ushort(hb) << 16);
    ra = a - __bfloat162float(ha);
    rb = b - __bfloat162float(hb);
}
__device__ __forceinline__ uint32_t pack2(float a, float b) {
    return (uint32_t)__bfloat16_as_ushort(__float2bfloat16(a)) |
           ((uint32_t)__bfloat16_as_ushort(__float2bfloat16(b)) << 16);
}

// ---------------- setup kernels ----------------------------------------------
__global__ void zero2_kernel(int* p1, int n1, int* p2, int n2) {
    int i = blockIdx.x * blockDim.x + threadIdx.x;
    int stride = gridDim.x * blockDim.x;
    for (int j = i; j < n1; j += stride) p1[j] = 0;
    for (int j = i; j < n2; j += stride) p2[j] = 0;
}

__global__ void deg_count_kernel(const int* __restrict__ suu, const int* __restrict__ duu,
                                 const int* __restrict__ sui, const int* __restrict__ dui,
                                 const int* __restrict__ siu, const int* __restrict__ diu,
                                 int* __restrict__ degi) {
    int i = blockIdx.x * blockDim.x + threadIdx.x;
    if (i >= NE) return;
    atomicAdd(&degi[0 * NN + suu[i]], 1);
    atomicAdd(&degi[1 * NN + duu[i]], 1);
    atomicAdd(&degi[2 * NN + sui[i]], 1);
    atomicAdd(&degi[3 * NN + dui[i]], 1);
    atomicAdd(&degi[4 * NN + siu[i]], 1);
    atomicAdd(&degi[5 * NN + diu[i]], 1);
}

__global__ void deg_finalize_kernel(const int* __restrict__ degi, float* __restrict__ deg) {
    int i = blockIdx.x * blockDim.x + threadIdx.x;
    if (i >= NN) return;
#pragma unroll
    for (int j = 0; j < 6; j++)
        deg[j * NN + i] = rsqrtf(fmaxf((float)degi[j * NN + i], 1.f));
}

__global__ void scan_s1(const int* __restrict__ degi, int* __restrict__ off,
                        int* __restrict__ bsum) {
    int et = blockIdx.y;
    const int* d = degi + (1 + 2 * et) * NN;
    int* o = off + et * NN;
    __shared__ int wsum[8], woff[8];
    int t = threadIdx.x;
    int base = blockIdx.x * 1024 + t * 4;
    int x[4];
#pragma unroll
    for (int j = 0; j < 4; j++) x[j] = (base + j < NN) ? d[base + j] : 0;
    int tl = x[0] + x[1] + x[2] + x[3];
    int incl = tl;
#pragma unroll
    for (int s = 1; s < 32; s <<= 1) {
        int y = __shfl_up_sync(0xffffffff, incl, s);
        if ((t & 31) >= s) incl += y;
    }
    if ((t & 31) == 31) wsum[t >> 5] = incl;
    __syncthreads();
    if (t == 0) {
        int a = 0;
#pragma unroll
        for (int k = 0; k < 8; k++) { woff[k] = a; a += wsum[k]; }
    }
    __syncthreads();
    int run = woff[t >> 5] + incl - tl;
#pragma unroll
    for (int j = 0; j < 4; j++) {
        if (base + j < NN) o[base + j] = run;
        run += x[j];
    }
    if (t == 255) bsum[et * 128 + blockIdx.x] = woff[7] + wsum[7];
}

__global__ void scan_s2(int* bsum) {
    int et = threadIdx.x;
    if (et < 3) {
        int a = 0;
        for (int i = 0; i < SCAN_NB; i++) {
            int t = bsum[et * 128 + i];
            bsum[et * 128 + i] = a;
            a += t;
        }
    }
}

__global__ void scan_s3(int* __restrict__ off, const int* __restrict__ bsum) {
    int et = blockIdx.y;
    int i = blockIdx.x * blockDim.x + threadIdx.x;
    if (i < NN) off[et * NN + i] += bsum[et * 128 + (i >> 10)];
}

__global__ void fill3_kernel(const int* __restrict__ s0, const int* __restrict__ d0,
                             const int* __restrict__ s1, const int* __restrict__ d1,
                             const int* __restrict__ s2, const int* __restrict__ d2,
                             const int* __restrict__ off, int* __restrict__ cur,
                             int* __restrict__ esrc) {
    int et = blockIdx.y;
    const int* src = (et == 0) ? s0 : (et == 1) ? s1 : s2;
    const int* dst = (et == 0) ? d0 : (et == 1) ? d1 : d2;
    int e = blockIdx.x * blockDim.x + threadIdx.x;
    if (e >= NE) return;
    int d = dst[e];
    int p = atomicAdd(&cur[et * NN + d], 1);
    esrc[(size_t)et * NE + off[et * NN + d] + p] = src[e];
}

// pre-split the 9 layer weight matrices (128x128 each) into bf16 hi/lo pairs
struct WPtrs { const float* w[9]; };
__global__ void wsplit_kernel(WPtrs wp, uint32_t* __restrict__ wh, uint32_t* __restrict__ wl) {
    int m = blockIdx.y;
    const float* W = wp.w[m];
    int i = blockIdx.x * blockDim.x + threadIdx.x;   // pair index, 0..8191
    if (i >= 128 * 64) return;
    float2 v = ((const float2*)W)[i];
    uint32_t hi;
    float ra, rb;
    split2(v.x, v.y, hi, ra, rb);
    wh[(size_t)m * 8192 + i] = hi;
    wl[(size_t)m * 8192 + i] = pack2(ra, rb);
}

// ---------------- 3-etype CSR gather, writes pre-split S ----------------------
// blockIdx.y = etype (0=uu from Xu, 1=ui from Xu, 2=iu from Xi)
// row value = rin[r] * sum_edges X[src]*rout[src]; stored as bf16 hi/lo pairs
__global__ __launch_bounds__(256) void gather3_kernel(
    const float* __restrict__ Xu, const float* __restrict__ Xi,
    const float* __restrict__ deg,
    const int* __restrict__ off, const int* __restrict__ esrc,
    uint32_t* __restrict__ Sh, uint32_t* __restrict__ Sl) {
    int et = blockIdx.y;
    const float* X = (et == 2) ? Xi : Xu;
    const float* rout;
    const float* rin;
    if (et == 0)      { rout = deg + 0 * NN; rin = deg + 1 * NN; }
    else if (et == 1) { rout = deg + 2 * NN; rin = deg + 3 * NN; }
    else              { rout = deg + 4 * NN; rin = deg + 5 * NN; }
    const int* o = off + et * NN;
    const int* es = esrc + (size_t)et * NE;
    uint32_t* ShO = Sh + (size_t)et * NP;
    uint32_t* SlO = Sl + (size_t)et * NP;

    int r = blockIdx.x * 8 + (threadIdx.x >> 5);
    if (r >= NN) return;
    int lane = threadIdx.x & 31;
    int b = __ldg(&o[r]);
    int e = (r + 1 < NN) ? __ldg(&o[r + 1]) : NE;
    float4 acc = make_float4(0.f, 0.f, 0.f, 0.f);
    int j = b;
    for (; j + 1 < e; j += 2) {
        int s0 = __ldg(&es[j]);
        int s1 = __ldg(&es[j + 1]);
        float r0 = __ldg(&rout[s0]);
        float r1 = __ldg(&rout[s1]);
        float4 x0 = *(const float4*)(X + (size_t)s0 * H + lane * 4);
        float4 x1 = *(const float4*)(X + (size_t)s1 * H + lane * 4);
        acc.x += x0.x * r0; acc.y += x0.y * r0;
        acc.z += x0.z * r0; acc.w += x0.w * r0;
        acc.x += x1.x * r1; acc.y += x1.y * r1;
        acc.z += x1.z * r1; acc.w += x1.w * r1;
    }
    if (j < e) {
        int s = __ldg(&es[j]);
        float rr = __ldg(&rout[s]);
        float4 xv = *(const float4*)(X + (size_t)s * H + lane * 4);
        acc.x += xv.x * rr; acc.y += xv.y * rr;
        acc.z += xv.z * rr; acc.w += xv.w * rr;
    }
    float ri = __ldg(&rin[r]);
    acc.x *= ri; acc.y *= ri; acc.z *= ri; acc.w *= ri;

    uint2 hi, lo;
    float ra, rb, rc, rd;
    split2(acc.x, acc.y, hi.x, ra, rb);
    split2(acc.z, acc.w, hi.y, rc, rd);
    lo.x = pack2(ra, rb);
    lo.y = pack2(rc, rd);
    *(uint2*)(ShO + (size_t)r * 64 + lane * 2) = hi;
    *(uint2*)(SlO + (size_t)r * 64 + lane * 2) = lo;
}

// ---------------- shared GEMM tile config ------------------------------------
#define BMROWS 64
#define ABUF 5120                  // 64 rows * 80B
#define BBUF 8192                  // 32 k-rows * 256B
#define BUFSZ (2 * ABUF + 2 * BBUF)
#define SM_BIAS (2 * BUFSZ)
#define TCSMEM (SM_BIAS + 1024)

// ---------------- merged embed GEMM (dense fp32 in; y=0 user, y=1 item) ------
__global__ __launch_bounds__(256, 3) void mma_embed_kernel(
    const float* __restrict__ Au, const float* __restrict__ Wu, const float* __restrict__ bu,
    const float* __restrict__ Ai, const float* __restrict__ Wi, const float* __restrict__ bi,
    float* __restrict__ Cu, float* __restrict__ Ci)
{
    extern __shared__ char sm[];
    const uint32_t sbase = smem_u32(sm);
    const int tid = threadIdx.x, lane = tid & 31, wid = tid >> 5;
    const int blockRow = blockIdx.x * BMROWS;
    const int wm = (wid & 3) * 16;
    const int wn = (wid >> 2) * 64;

    const float* A;
    const float* W;
    const float* bias;
    float* C;
    int K;
    if (blockIdx.y == 0) { A = Au; W = Wu; bias = bu; C = Cu; K = D_U; }
    else                 { A = Ai; W = Wi; bias = bi; C = Ci; K = D_I; }

    if (tid < 128) ((float*)(sm + SM_BIAS))[tid] = bias[tid];

    float acc[8][4];
#pragma unroll
    for (int j = 0; j < 8; j++)
#pragma unroll
        for (int k = 0; k < 4; k++) acc[j][k] = 0.f;

    const int nch = (K + 31) / 32;

    const int r8 = lane & 7, sel = lane >> 3;
    const int a_row = r8 + ((sel & 1) << 3);
    const int a_kb  = (sel >> 1) << 4;
    const int b_csel = sel >> 1;

    auto load_chunk = [&](int ch) {
        const int k0 = ch * 32;
        char* buf = sm + (ch & 1) * BUFSZ;
#pragma unroll
        for (int i = 0; i < 2; i++) {
            int idx = tid + i * 256;
            int row = idx >> 3, q = idx & 7;
            int gm = blockRow + row, gk = k0 + q * 4;
            float4 v = make_float4(0.f, 0.f, 0.f, 0.f);
            if (gm < NN && gk + 3 < K) v = *(const float4*)(A + (size_t)gm * K + gk);
            else if (gm < NN) {
                const float* ap = A + (size_t)gm * K + gk;
                if (gk + 0 < K) v.x = ap[0];
                if (gk + 1 < K) v.y = ap[1];
                if (gk + 2 < K) v.z = ap[2];
                if (gk + 3 < K) v.w = ap[3];
            }
            float rx, ry, rz, rw;
            uint2 hi, lo;
            split2(v.x, v.y, hi.x, rx, ry);
            split2(v.z, v.w, hi.y, rz, rw);
            lo.x = pack2(rx, ry);
            lo.y = pack2(rz, rw);
            *(uint2*)(buf + (size_t)row * 80 + q * 8) = hi;
            *(uint2*)(buf + ABUF + (size_t)row * 80 + q * 8) = lo;
        }
#pragma unroll
        for (int i = 0; i < 4; i++) {
            int idx = tid + i * 256;
            int kk = idx >> 5, q = idx & 31;
            int gk = k0 + kk;
            float4 v = make_float4(0.f, 0.f, 0.f, 0.f);
            if (gk < K) v = *(const float4*)(W + (size_t)gk * 128 + q * 4);
            float rx, ry, rz, rw;
            uint2 hi, lo;
            split2(v.x, v.y, hi.x, rx, ry);
            split2(v.z, v.w, hi.y, rz, rw);
            lo.x = pack2(rx, ry);
            lo.y = pack2(rz, rw);
            uint32_t o = (uint32_t)kk * 256 + ((((uint32_t)(q >> 1)) ^ (kk & 7)) << 4) + (q & 1) * 8;
            *(uint2*)(buf + 2 * ABUF + o) = hi;
            *(uint2*)(buf + 2 * ABUF + BBUF + o) = lo;
        }
    };

    load_chunk(0);
    __syncthreads();

    for (int ch = 0; ch < nch; ch++) {
        if (ch + 1 < nch) load_chunk(ch + 1);
        const uint32_t bufb = sbase + (ch & 1) * BUFSZ;

#pragma unroll
        for (int h = 0; h < 2; h++) {
            uint32_t ah[4], al[4], bf[4][4];
            {
                uint32_t aaddr = bufb + (wm + a_row) * 80 + h * 32 + a_kb;
                ldm_x4(ah, aaddr);
                ldm_x4(al, aaddr + ABUF);
            }
            const int kk = h * 16 + a_row;
            const uint32_t brow = bufb + 2 * ABUF + (uint32_t)kk * 256;
#pragma unroll
            for (int j = 0; j < 4; j++) {
                uint32_t chunk = (uint32_t)((wn >> 3) + j * 2 + b_csel) ^ (kk & 7);
                ldm_x4_t(bf[j], brow + chunk * 16);
            }
#pragma unroll
            for (int j = 0; j < 4; j++) {
                mma_bf16(acc[2 * j],     ah, bf[j][0], bf[j][1]);
                mma_bf16(acc[2 * j + 1], ah, bf[j][2], bf[j][3]);
                mma_bf16(acc[2 * j],     al, bf[j][0], bf[j][1]);
                mma_bf16(acc[2 * j + 1], al, bf[j][2], bf[j][3]);
            }
#pragma unroll
            for (int j = 0; j < 4; j++) {
                uint32_t chunk = (uint32_t)((wn >> 3) + j * 2 + b_csel) ^ (kk & 7);
                ldm_x4_t(bf[j], brow + BBUF + chunk * 16);
            }
#pragma unroll
            for (int j = 0; j < 4; j++) {
                mma_bf16(acc[2 * j],     ah, bf[j][0], bf[j][1]);
                mma_bf16(acc[2 * j + 1], ah, bf[j][2], bf[j][3]);
            }
        }
        __syncthreads();
    }

    const float* bs = (const float*)(sm + SM_BIAS);
    const int g = lane >> 2;
    const int t2 = (lane & 3) * 2;
#pragma unroll
    for (int half = 0; half < 2; half++) {
        int row = blockRow + wm + g + half * 8;
        if (row >= NN) continue;
        float* cp = C + (size_t)row * 128;
#pragma unroll
        for (int nt = 0; nt < 8; nt++) {
            int col = wn + nt * 8 + t2;
            float v0 = acc[nt][half * 2 + 0] + bs[col];
            float v1 = acc[nt][half * 2 + 1] + bs[col + 1];
            *(float2*)(cp + col) = make_float2(v0, v1);
        }
    }
}

// ---------------- layer GEMM: pre-split inputs, one launch, grid.y out --------
// y==0: Cu = relu?(Suu@Wuu+buu) + relu?(Siu@Wiu+biu)   (dual-term, K=128 each)
// y==1: Ci = relu?(Sui@Wui+bui)
__global__ __launch_bounds__(256, 2) void layer_gemm_kernel(
    const uint32_t* __restrict__ Sh, const uint32_t* __restrict__ Sl,
    const uint32_t* __restrict__ Wh, const uint32_t* __restrict__ Wl,
    const float* __restrict__ buu, const float* __restrict__ biu,
    const float* __restrict__ bui,
    float* __restrict__ Cu, float* __restrict__ Ci, int layer, int doRelu)
{
    extern __shared__ char sm[];
    const uint32_t sbase = smem_u32(sm);
    const int tid = threadIdx.x, lane = tid & 31, wid = tid >> 5;
    const int blockRow = blockIdx.x * BMROWS;
    const int wm = (wid & 3) * 16;
    const int wn = (wid >> 2) * 64;

    int plane[2], widx[2], nterm;
    if (blockIdx.y == 0) {
        plane[0] = 0; widx[0] = layer * 3 + 0;   // uu
        plane[1] = 2; widx[1] = layer * 3 + 2;   // iu
        nterm = 2;
        if (tid < 128) {
            ((float*)(sm + SM_BIAS))[tid] = buu[tid];
            ((float*)(sm + SM_BIAS + 512))[tid] = biu[tid];
        }
    } else {
        plane[0] = 1; widx[0] = layer * 3 + 1;   // ui
        plane[1] = 1; widx[1] = layer * 3 + 1;
        nterm = 1;
        if (tid < 128) ((float*)(sm + SM_BIAS))[tid] = bui[tid];
    }
    float* C = (blockIdx.y == 0) ? Cu : Ci;

    float acc[8][4], out[8][4];
#pragma unroll
    for (int j = 0; j < 8; j++)
#pragma unroll
        for (int k = 0; k < 4; k++) { acc[j][k] = 0.f; out[j][k] = 0.f; }

    const int r8 = lane & 7, sel = lane >> 3;
    const int a_row = r8 + ((sel & 1) << 3);
    const int a_kb  = (sel >> 1) << 4;
    const int b_csel = sel >> 1;
    const int g = lane >> 2;
    const int t2 = (lane & 3) * 2;

    // chunk index ci in [0, 4*nterm): term = ci>>2, k0 = (ci&3)*32
    auto load_chunk = [&](int ci) {
        const int term = ci >> 2;
        const int k0 = (ci & 3) * 32;
        const uint32_t* Ah = Sh + (size_t)plane[term] * NP;
        const uint32_t* Al = Sl + (size_t)plane[term] * NP;
        const uint32_t* Bh = Wh + (size_t)widx[term] * 8192;
        const uint32_t* Bl = Wl + (size_t)widx[term] * 8192;
        char* buf = sm + (ci & 1) * BUFSZ;
        // A tile: 64 rows x 8 uint2-slots (copy-only)
#pragma unroll
        for (int i = 0; i < 2; i++) {
            int idx = tid + i * 256;
            int row = idx >> 3, q = idx & 7;
            int gm = blockRow + row;
            uint2 hi = make_uint2(0u, 0u), lo = make_uint2(0u, 0u);
            if (gm < NN) {
                size_t o = (size_t)gm * 64 + (k0 >> 1) + q * 2;
                hi = *(const uint2*)(Ah + o);
                lo = *(const uint2*)(Al + o);
            }
            *(uint2*)(buf + (size_t)row * 80 + q * 8) = hi;
            *(uint2*)(buf + ABUF + (size_t)row * 80 + q * 8) = lo;
        }
        // B tile: 32 k-rows x 32 uint2-slots, XOR chunk swizzle (copy-only)
#pragma unroll
        for (int i = 0; i < 4; i++) {
            int idx = tid + i * 256;
            int kk = idx >> 5, q = idx & 31;
            size_t go = (size_t)(k0 + kk) * 64 + q * 2;
            uint2 hi = *(const uint2*)(Bh + go);
            uint2 lo = *(const uint2*)(Bl + go);
            uint32_t o = (uint32_t)kk * 256 + ((((uint32_t)(q >> 1)) ^ (kk & 7)) << 4) + (q & 1) * 8;
            *(uint2*)(buf + 2 * ABUF + o) = hi;
            *(uint2*)(buf + 2 * ABUF + BBUF + o) = lo;
        }
    };

    const int total = nterm * 4;
    load_chunk(0);
    __syncthreads();

    for (int ci = 0; ci < total; ci++) {
        if (ci + 1 < total) load_chunk(ci + 1);
        const uint32_t bufb = sbase + (ci & 1) * BUFSZ;

#pragma unroll
        for (int h = 0; h < 2; h++) {
            uint32_t ah[4], al[4], bf[4][4];
            {
                uint32_t aaddr = bufb + (wm + a_row) * 80 + h * 32 + a_kb;
                ldm_x4(ah, aaddr);
                ldm_x4(al, aaddr + ABUF);
            }
            const int kk = h * 16 + a_row;
            const uint32_t brow = bufb + 2 * ABUF + (uint32_t)kk * 256;
#pragma unroll
            for (int j = 0; j < 4; j++) {
                uint32_t chunk = (uint32_t)((wn >> 3) + j * 2 + b_csel) ^ (kk & 7);
                ldm_x4_t(bf[j], brow + chunk * 16);
            }
#pragma unroll
            for (int j = 0; j < 4; j++) {
                mma_bf16(acc[2 * j],     ah, bf[j][0], bf[j][1]);
                mma_bf16(acc[2 * j + 1], ah, bf[j][2], bf[j][3]);
                mma_bf16(acc[2 * j],     al, bf[j][0], bf[j][1]);
                mma_bf16(acc[2 * j + 1], al, bf[j][2], bf[j][3]);
            }
#pragma unroll
            for (int j = 0; j < 4; j++) {
                uint32_t chunk = (uint32_t)((wn >> 3) + j * 2 + b_csel) ^ (kk & 7);
                ldm_x4_t(bf[j], brow + BBUF + chunk * 16);
            }
#pragma unroll
            for (int j = 0; j < 4; j++) {
                mma_bf16(acc[2 * j],     ah, bf[j][0], bf[j][1]);
                mma_bf16(acc[2 * j + 1], ah, bf[j][2], bf[j][3]);
            }
        }
        __syncthreads();

        if ((ci & 3) == 3) {
            // fold this term: out += maybe_relu(acc + bias[term]); reset acc
            const float* bt = (const float*)(sm + SM_BIAS + (ci >> 2) * 512);
#pragma unroll
            for (int nt = 0; nt < 8; nt++)
#pragma unroll
                for (int half = 0; half < 2; half++)
#pragma unroll
                    for (int j2 = 0; j2 < 2; j2++) {
                        int col = wn + nt * 8 + t2 + j2;
                        float v = acc[nt][half * 2 + j2] + bt[col];
                        if (doRelu) v = fmaxf(v, 0.f);
                        out[nt][half * 2 + j2] += v;
                        acc[nt][half * 2 + j2] = 0.f;
                    }
        }
    }

    // epilogue: write out
#pragma unroll
    for (int half = 0; half < 2; half++) {
        int row = blockRow + wm + g + half * 8;
        if (row >= NN) continue;
        float* cp = C + (size_t)row * 128;
#pragma unroll
        for (int nt = 0; nt < 8; nt++) {
            int col = wn + nt * 8 + t2;
            *(float2*)(cp + col) = make_float2(out[nt][half * 2 + 0],
                                               out[nt][half * 2 + 1]);
        }
    }
}

// ---------------- host orchestration -----------------------------------------
extern "C" void kernel_launch(void* const* d_in, const int* in_sizes, int n_in,
                              void* d_out, int out_size) {
    const float* feat_user = (const float*)d_in[0];
    const float* feat_item = (const float*)d_in[1];
    const int* src_uu = (const int*)d_in[2];
    const int* dst_uu = (const int*)d_in[3];
    const int* src_ui = (const int*)d_in[4];
    const int* dst_ui = (const int*)d_in[5];
    const int* src_iu = (const int*)d_in[6];
    const int* dst_iu = (const int*)d_in[7];
    const float* We_u = (const float*)d_in[8];
    const float* be_u = (const float*)d_in[9];
    const float* We_i = (const float*)d_in[10];
    const float* be_i = (const float*)d_in[11];
    const float* W[3][3];
    const float* B[3][3];
    for (int l = 0; l < 3; l++)
        for (int e = 0; e < 3; e++) {
            W[l][e] = (const float*)d_in[12 + l * 6 + e * 2];
            B[l][e] = (const float*)d_in[12 + l * 6 + e * 2 + 1];
        }

    float *hu, *hi, *deg;
    uint32_t *Sh, *Sl, *Wh, *Wl;
    int *degi, *off, *cur, *esrc, *bsum;
    cudaGetSymbolAddress((void**)&hu, g_hu);
    cudaGetSymbolAddress((void**)&hi, g_hi);
    cudaGetSymbolAddress((void**)&Sh, g_Sh);
    cudaGetSymbolAddress((void**)&Sl, g_Sl);
    cudaGetSymbolAddress((void**)&Wh, g_Wh);
    cudaGetSymbolAddress((void**)&Wl, g_Wl);
    cudaGetSymbolAddress((void**)&deg, g_deg);
    cudaGetSymbolAddress((void**)&degi, g_degi);
    cudaGetSymbolAddress((void**)&off, g_off);
    cudaGetSymbolAddress((void**)&cur, g_cur);
    cudaGetSymbolAddress((void**)&esrc, g_esrc);
    cudaGetSymbolAddress((void**)&bsum, g_bsum);
    float* out = (float*)d_out;

    cudaFuncSetAttribute(mma_embed_kernel,
                         cudaFuncAttributeMaxDynamicSharedMemorySize, TCSMEM);
    cudaFuncSetAttribute(layer_gemm_kernel,
                         cudaFuncAttributeMaxDynamicSharedMemorySize, TCSMEM);

    // ---- degree + CSR build + weight pre-split ----
    zero2_kernel<<<256, 256>>>(degi, 6 * NN, cur, 3 * NN);
    deg_count_kernel<<<(NE + 255) / 256, 256>>>(src_uu, dst_uu, src_ui, dst_ui,
                                                src_iu, dst_iu, degi);
    deg_finalize_kernel<<<(NN + 255) / 256, 256>>>(degi, deg);
    {
        dim3 g1(SCAN_NB, 3);
        scan_s1<<<g1, 256>>>(degi, off, bsum);
        scan_s2<<<1, 32>>>(bsum);
        dim3 g3((NN + 255) / 256, 3);
        scan_s3<<<g3, 256>>>(off, bsum);
    }
    {
        dim3 gf((NE + 255) / 256, 3);
        fill3_kernel<<<gf, 256>>>(src_uu, dst_uu, src_ui, dst_ui, src_iu, dst_iu,
                                  off, cur, esrc);
    }
    {
        WPtrs wp;
        for (int l = 0; l < 3; l++)
            for (int e = 0; e < 3; e++) wp.w[l * 3 + e] = W[l][e];
        dim3 gw((128 * 64 + 255) / 256, 9);
        wsplit_kernel<<<gw, 256>>>(wp, Wh, Wl);
    }

    int grid = (NN + BMROWS - 1) / BMROWS;

    // ---- embed (merged dense GEMM) ----
    {
        dim3 ge(grid, 2);
        mma_embed_kernel<<<ge, 256, TCSMEM>>>(feat_user, We_u, be_u,
                                              feat_item, We_i, be_i, hu, hi);
    }

    // ---- layers: 1 gather launch + 1 GEMM launch each ----
    int cur_pp = 0;
    for (int l = 0; l < 3; l++) {
        int relu = (l < 2) ? 1 : 0;
        float* hu_cur = hu + (size_t)cur_pp * NUH;
        float* hi_cur = hi + (size_t)cur_pp * NUH;
        float* hu_nxt = (l == 2) ? out : hu + (size_t)(1 - cur_pp) * NUH;
        float* hi_nxt = (l == 2) ? out + (size_t)NUH : hi + (size_t)(1 - cur_pp) * NUH;

        dim3 gg((NN + 7) / 8, 3);
        gather3_kernel<<<gg, 256>>>(hu_cur, hi_cur, deg, off, esrc, Sh, Sl);

        dim3 lg(grid, 2);
        layer_gemm_kernel<<<lg, 256, TCSMEM>>>(Sh, Sl, Wh, Wl,
                                               B[l][0], B[l][2], B[l][1],
                                               hu_nxt, hi_nxt, l, relu);
        cur_pp ^= 1;
    }
    (void)in_sizes; (void)n_in; (void)out_size;
}

// round 15
// speedup vs baseline: 1.4124x; 1.0745x over previous
#include <cuda_runtime.h>
#include <cuda_bf16.h>
#include <cstdint>

#define NN  100000
#define NE  500000
#define H   128
#define D_U 256
#define D_I 300
#define NUH (NN * H)
#define NP  (NN * 64)         // uint32 pairs per S plane
#define SCAN_NB 98            // ceil(NN/1024)

// ---------------- scratch (static device globals; no allocation) -------------
__device__ float    g_hu[2][NUH];
__device__ float    g_hi[2][NUH];
__device__ uint32_t g_Sh[3][NP];   // gathered rows, bf16-hi pairs: 0=uu, 1=ui, 2=iu
__device__ uint32_t g_Sl[3][NP];   // bf16-lo pairs
__device__ uint32_t g_Wh[9][128 * 64]; // layer weights pre-split (idx = l*3+e)
__device__ uint32_t g_Wl[9][128 * 64];
__device__ float    g_deg[6][NN];  // rsqrt: 0 out_uu, 1 in_uu, 2 out_ui, 3 in_ui, 4 out_iu, 5 in_iu
__device__ int      g_degi[6][NN];
__device__ int      g_off[3][NN];
__device__ int      g_cur[3][NN];
__device__ int      g_esrc[3][NE];
__device__ int      g_bsum[3][128];

// ---------------- small helpers ----------------------------------------------
__device__ __forceinline__ uint32_t smem_u32(const void* p) {
    uint32_t a;
    asm("{ .reg .u64 t; cvta.to.shared.u64 t, %1; cvt.u32.u64 %0, t; }" : "=r"(a) : "l"(p));
    return a;
}
__device__ __forceinline__ void ldm_x4(uint32_t* r, uint32_t addr) {
    asm volatile("ldmatrix.sync.aligned.m8n8.x4.shared.b16 {%0,%1,%2,%3}, [%4];"
                 : "=r"(r[0]), "=r"(r[1]), "=r"(r[2]), "=r"(r[3]) : "r"(addr));
}
__device__ __forceinline__ void ldm_x4_t(uint32_t* r, uint32_t addr) {
    asm volatile("ldmatrix.sync.aligned.m8n8.x4.trans.shared.b16 {%0,%1,%2,%3}, [%4];"
                 : "=r"(r[0]), "=r"(r[1]), "=r"(r[2]), "=r"(r[3]) : "r"(addr));
}
__device__ __forceinline__ void mma_bf16(float* d, const uint32_t* a, uint32_t b0, uint32_t b1) {
    asm volatile("mma.sync.aligned.m16n8k16.row.col.f32.bf16.bf16.f32 "
                 "{%0,%1,%2,%3}, {%4,%5,%6,%7}, {%8,%9}, {%0,%1,%2,%3};"
                 : "+f"(d[0]), "+f"(d[1]), "+f"(d[2]), "+f"(d[3])
                 : "r"(a[0]), "r"(a[1]), "r"(a[2]), "r"(a[3]), "r"(b0), "r"(b1));
}
__device__ __forceinline__ void split2(float a, float b, uint32_t& hi, float& ra, float& rb) {
    __nv_bfloat16 ha = __float2bfloat16(a), hb = __float2bfloat16(b);
    hi = (uint32_t)__bfloat16_as_ushort(ha) | ((uint32_t)__bfloat16_as_ushort(hb) << 16);
    ra = a - __bfloat162float(ha);
    rb = b - __bfloat162float(hb);
}
__device__ __forceinline__ uint32_t pack2(float a, float b) {
    return (uint32_t)__bfloat16_as_ushort(__float2bfloat16(a)) |
           ((uint32_t)__bfloat16_as_ushort(__float2bfloat16(b)) << 16);
}
__device__ __forceinline__ void cp_async8(uint32_t saddr, const void* gaddr, int src_sz) {
    asm volatile("cp.async.ca.shared.global [%0], [%1], 8, %2;"
                 :: "r"(saddr), "l"(gaddr), "r"(src_sz) : "memory");
}
#define CP_COMMIT() asm volatile("cp.async.commit_group;" ::: "memory")
#define CP_WAIT0()  asm volatile("cp.async.wait_group 0;" ::: "memory")

// ---------------- setup kernels ----------------------------------------------
__global__ void zero2_kernel(int* p1, int n1, int* p2, int n2) {
    int i = blockIdx.x * blockDim.x + threadIdx.x;
    int stride = gridDim.x * blockDim.x;
    for (int j = i; j < n1; j += stride) p1[j] = 0;
    for (int j = i; j < n2; j += stride) p2[j] = 0;
}

__global__ void deg_count_kernel(const int* __restrict__ suu, const int* __restrict__ duu,
                                 const int* __restrict__ sui, const int* __restrict__ dui,
                                 const int* __restrict__ siu, const int* __restrict__ diu,
                                 int* __restrict__ degi) {
    int i = blockIdx.x * blockDim.x + threadIdx.x;
    if (i >= NE) return;
    atomicAdd(&degi[0 * NN + suu[i]], 1);
    atomicAdd(&degi[1 * NN + duu[i]], 1);
    atomicAdd(&degi[2 * NN + sui[i]], 1);
    atomicAdd(&degi[3 * NN + dui[i]], 1);
    atomicAdd(&degi[4 * NN + siu[i]], 1);
    atomicAdd(&degi[5 * NN + diu[i]], 1);
}

__global__ void deg_finalize_kernel(const int* __restrict__ degi, float* __restrict__ deg) {
    int i = blockIdx.x * blockDim.x + threadIdx.x;
    if (i >= NN) return;
#pragma unroll
    for (int j = 0; j < 6; j++)
        deg[j * NN + i] = rsqrtf(fmaxf((float)degi[j * NN + i], 1.f));
}

__global__ void scan_s1(const int* __restrict__ degi, int* __restrict__ off,
                        int* __restrict__ bsum) {
    int et = blockIdx.y;
    const int* d = degi + (1 + 2 * et) * NN;
    int* o = off + et * NN;
    __shared__ int wsum[8], woff[8];
    int t = threadIdx.x;
    int base = blockIdx.x * 1024 + t * 4;
    int x[4];
#pragma unroll
    for (int j = 0; j < 4; j++) x[j] = (base + j < NN) ? d[base + j] : 0;
    int tl = x[0] + x[1] + x[2] + x[3];
    int incl = tl;
#pragma unroll
    for (int s = 1; s < 32; s <<= 1) {
        int y = __shfl_up_sync(0xffffffff, incl, s);
        if ((t & 31) >= s) incl += y;
    }
    if ((t & 31) == 31) wsum[t >> 5] = incl;
    __syncthreads();
    if (t == 0) {
        int a = 0;
#pragma unroll
        for (int k = 0; k < 8; k++) { woff[k] = a; a += wsum[k]; }
    }
    __syncthreads();
    int run = woff[t >> 5] + incl - tl;
#pragma unroll
    for (int j = 0; j < 4; j++) {
        if (base + j < NN) o[base + j] = run;
        run += x[j];
    }
    if (t == 255) bsum[et * 128 + blockIdx.x] = woff[7] + wsum[7];
}

__global__ void scan_s2(int* bsum) {
    int et = threadIdx.x;
    if (et < 3) {
        int a = 0;
        for (int i = 0; i < SCAN_NB; i++) {
            int t = bsum[et * 128 + i];
            bsum[et * 128 + i] = a;
            a += t;
        }
    }
}

__global__ void scan_s3(int* __restrict__ off, const int* __restrict__ bsum) {
    int et = blockIdx.y;
    int i = blockIdx.x * blockDim.x + threadIdx.x;
    if (i < NN) off[et * NN + i] += bsum[et * 128 + (i >> 10)];
}

__global__ void fill3_kernel(const int* __restrict__ s0, const int* __restrict__ d0,
                             const int* __restrict__ s1, const int* __restrict__ d1,
                             const int* __restrict__ s2, const int* __restrict__ d2,
                             const int* __restrict__ off, int* __restrict__ cur,
                             int* __restrict__ esrc) {
    int et = blockIdx.y;
    const int* src = (et == 0) ? s0 : (et == 1) ? s1 : s2;
    const int* dst = (et == 0) ? d0 : (et == 1) ? d1 : d2;
    int e = blockIdx.x * blockDim.x + threadIdx.x;
    if (e >= NE) return;
    int d = dst[e];
    int p = atomicAdd(&cur[et * NN + d], 1);
    esrc[(size_t)et * NE + off[et * NN + d] + p] = src[e];
}

// pre-split the 9 layer weight matrices (128x128 each) into bf16 hi/lo pairs
struct WPtrs { const float* w[9]; };
__global__ void wsplit_kernel(WPtrs wp, uint32_t* __restrict__ wh, uint32_t* __restrict__ wl) {
    int m = blockIdx.y;
    const float* W = wp.w[m];
    int i = blockIdx.x * blockDim.x + threadIdx.x;   // pair index, 0..8191
    if (i >= 128 * 64) return;
    float2 v = ((const float2*)W)[i];
    uint32_t hi;
    float ra, rb;
    split2(v.x, v.y, hi, ra, rb);
    wh[(size_t)m * 8192 + i] = hi;
    wl[(size_t)m * 8192 + i] = pack2(ra, rb);
}

// ---------------- 3-etype CSR gather, writes pre-split S ----------------------
__global__ __launch_bounds__(256) void gather3_kernel(
    const float* __restrict__ Xu, const float* __restrict__ Xi,
    const float* __restrict__ deg,
    const int* __restrict__ off, const int* __restrict__ esrc,
    uint32_t* __restrict__ Sh, uint32_t* __restrict__ Sl) {
    int et = blockIdx.y;
    const float* X = (et == 2) ? Xi : Xu;
    const float* rout;
    const float* rin;
    if (et == 0)      { rout = deg + 0 * NN; rin = deg + 1 * NN; }
    else if (et == 1) { rout = deg + 2 * NN; rin = deg + 3 * NN; }
    else              { rout = deg + 4 * NN; rin = deg + 5 * NN; }
    const int* o = off + et * NN;
    const int* es = esrc + (size_t)et * NE;
    uint32_t* ShO = Sh + (size_t)et * NP;
    uint32_t* SlO = Sl + (size_t)et * NP;

    int r = blockIdx.x * 8 + (threadIdx.x >> 5);
    if (r >= NN) return;
    int lane = threadIdx.x & 31;
    int b = __ldg(&o[r]);
    int e = (r + 1 < NN) ? __ldg(&o[r + 1]) : NE;
    float4 acc = make_float4(0.f, 0.f, 0.f, 0.f);
    int j = b;
    for (; j + 1 < e; j += 2) {
        int s0 = __ldg(&es[j]);
        int s1 = __ldg(&es[j + 1]);
        float r0 = __ldg(&rout[s0]);
        float r1 = __ldg(&rout[s1]);
        float4 x0 = *(const float4*)(X + (size_t)s0 * H + lane * 4);
        float4 x1 = *(const float4*)(X + (size_t)s1 * H + lane * 4);
        acc.x += x0.x * r0; acc.y += x0.y * r0;
        acc.z += x0.z * r0; acc.w += x0.w * r0;
        acc.x += x1.x * r1; acc.y += x1.y * r1;
        acc.z += x1.z * r1; acc.w += x1.w * r1;
    }
    if (j < e) {
        int s = __ldg(&es[j]);
        float rr = __ldg(&rout[s]);
        float4 xv = *(const float4*)(X + (size_t)s * H + lane * 4);
        acc.x += xv.x * rr; acc.y += xv.y * rr;
        acc.z += xv.z * rr; acc.w += xv.w * rr;
    }
    float ri = __ldg(&rin[r]);
    acc.x *= ri; acc.y *= ri; acc.z *= ri; acc.w *= ri;

    uint2 hi, lo;
    float ra, rb, rc, rd;
    split2(acc.x, acc.y, hi.x, ra, rb);
    split2(acc.z, acc.w, hi.y, rc, rd);
    lo.x = pack2(ra, rb);
    lo.y = pack2(rc, rd);
    *(uint2*)(ShO + (size_t)r * 64 + lane * 2) = hi;
    *(uint2*)(SlO + (size_t)r * 64 + lane * 2) = lo;
}

// ---------------- shared GEMM tile config ------------------------------------
#define BMROWS 64
#define ABUF 5120                  // 64 rows * 80B
#define BBUF 8192                  // 32 k-rows * 256B
#define BUFSZ (2 * ABUF + 2 * BBUF)
#define SM_BIAS (2 * BUFSZ)
#define TCSMEM (SM_BIAS + 1024)

// ---------------- merged embed GEMM (dense fp32 in; register-prefetch) -------
__global__ __launch_bounds__(256, 2) void mma_embed_kernel(
    const float* __restrict__ Au, const float* __restrict__ Wu, const float* __restrict__ bu,
    const float* __restrict__ Ai, const float* __restrict__ Wi, const float* __restrict__ bi,
    float* __restrict__ Cu, float* __restrict__ Ci)
{
    extern __shared__ char sm[];
    const uint32_t sbase = smem_u32(sm);
    const int tid = threadIdx.x, lane = tid & 31, wid = tid >> 5;
    const int blockRow = blockIdx.x * BMROWS;
    const int wm = (wid & 3) * 16;
    const int wn = (wid >> 2) * 64;

    const float* A;
    const float* W;
    const float* bias;
    float* C;
    int K;
    if (blockIdx.y == 0) { A = Au; W = Wu; bias = bu; C = Cu; K = D_U; }
    else                 { A = Ai; W = Wi; bias = bi; C = Ci; K = D_I; }

    if (tid < 128) ((float*)(sm + SM_BIAS))[tid] = bias[tid];

    float acc[8][4];
#pragma unroll
    for (int j = 0; j < 8; j++)
#pragma unroll
        for (int k = 0; k < 4; k++) acc[j][k] = 0.f;

    const int nch = (K + 31) / 32;

    const int r8 = lane & 7, sel = lane >> 3;
    const int a_row = r8 + ((sel & 1) << 3);
    const int a_kb  = (sel >> 1) << 4;
    const int b_csel = sel >> 1;

    float4 pa[2], pb[4];

    auto fetch = [&](int ch) {
        const int k0 = ch * 32;
#pragma unroll
        for (int i = 0; i < 2; i++) {
            int idx = tid + i * 256;
            int row = idx >> 3, q = idx & 7;
            int gm = blockRow + row, gk = k0 + q * 4;
            float4 v = make_float4(0.f, 0.f, 0.f, 0.f);
            if (gm < NN && gk + 3 < K) v = *(const float4*)(A + (size_t)gm * K + gk);
            else if (gm < NN) {
                const float* ap = A + (size_t)gm * K + gk;
                if (gk + 0 < K) v.x = ap[0];
                if (gk + 1 < K) v.y = ap[1];
                if (gk + 2 < K) v.z = ap[2];
                if (gk + 3 < K) v.w = ap[3];
            }
            pa[i] = v;
        }
#pragma unroll
        for (int i = 0; i < 4; i++) {
            int idx = tid + i * 256;
            int kk = idx >> 5, q = idx & 31;
            int gk = k0 + kk;
            pb[i] = (gk < K) ? *(const float4*)(W + (size_t)gk * 128 + q * 4)
                             : make_float4(0.f, 0.f, 0.f, 0.f);
        }
    };

    auto store_chunk = [&](int ch) {
        char* buf = sm + (ch & 1) * BUFSZ;
#pragma unroll
        for (int i = 0; i < 2; i++) {
            int idx = tid + i * 256;
            int row = idx >> 3, q = idx & 7;
            float4 v = pa[i];
            float rx, ry, rz, rw;
            uint2 hi, lo;
            split2(v.x, v.y, hi.x, rx, ry);
            split2(v.z, v.w, hi.y, rz, rw);
            lo.x = pack2(rx, ry);
            lo.y = pack2(rz, rw);
            *(uint2*)(buf + (size_t)row * 80 + q * 8) = hi;
            *(uint2*)(buf + ABUF + (size_t)row * 80 + q * 8) = lo;
        }
#pragma unroll
        for (int i = 0; i < 4; i++) {
            int idx = tid + i * 256;
            int kk = idx >> 5, q = idx & 31;
            float4 v = pb[i];
            float rx, ry, rz, rw;
            uint2 hi, lo;
            split2(v.x, v.y, hi.x, rx, ry);
            split2(v.z, v.w, hi.y, rz, rw);
            lo.x = pack2(rx, ry);
            lo.y = pack2(rz, rw);
            uint32_t o = (uint32_t)kk * 256 + ((((uint32_t)(q >> 1)) ^ (kk & 7)) << 4) + (q & 1) * 8;
            *(uint2*)(buf + 2 * ABUF + o) = hi;
            *(uint2*)(buf + 2 * ABUF + BBUF + o) = lo;
        }
    };

    fetch(0);
    store_chunk(0);
    __syncthreads();

    for (int ch = 0; ch < nch; ch++) {
        if (ch + 1 < nch) fetch(ch + 1);   // LDG issued; stall deferred to store
        const uint32_t bufb = sbase + (ch & 1) * BUFSZ;

#pragma unroll
        for (int h = 0; h < 2; h++) {
            uint32_t ah[4], al[4], bf[4][4];
            {
                uint32_t aaddr = bufb + (wm + a_row) * 80 + h * 32 + a_kb;
                ldm_x4(ah, aaddr);
                ldm_x4(al, aaddr + ABUF);
            }
            const int kk = h * 16 + a_row;
            const uint32_t brow = bufb + 2 * ABUF + (uint32_t)kk * 256;
#pragma unroll
            for (int j = 0; j < 4; j++) {
                uint32_t chunk = (uint32_t)((wn >> 3) + j * 2 + b_csel) ^ (kk & 7);
                ldm_x4_t(bf[j], brow + chunk * 16);
            }
#pragma unroll
            for (int j = 0; j < 4; j++) {
                mma_bf16(acc[2 * j],     ah, bf[j][0], bf[j][1]);
                mma_bf16(acc[2 * j + 1], ah, bf[j][2], bf[j][3]);
                mma_bf16(acc[2 * j],     al, bf[j][0], bf[j][1]);
                mma_bf16(acc[2 * j + 1], al, bf[j][2], bf[j][3]);
            }
#pragma unroll
            for (int j = 0; j < 4; j++) {
                uint32_t chunk = (uint32_t)((wn >> 3) + j * 2 + b_csel) ^ (kk & 7);
                ldm_x4_t(bf[j], brow + BBUF + chunk * 16);
            }
#pragma unroll
            for (int j = 0; j < 4; j++) {
                mma_bf16(acc[2 * j],     ah, bf[j][0], bf[j][1]);
                mma_bf16(acc[2 * j + 1], ah, bf[j][2], bf[j][3]);
            }
        }

        if (ch + 1 < nch) store_chunk(ch + 1);
        __syncthreads();
    }

    const float* bs = (const float*)(sm + SM_BIAS);
    const int g = lane >> 2;
    const int t2 = (lane & 3) * 2;
#pragma unroll
    for (int half = 0; half < 2; half++) {
        int row = blockRow + wm + g + half * 8;
        if (row >= NN) continue;
        float* cp = C + (size_t)row * 128;
#pragma unroll
        for (int nt = 0; nt < 8; nt++) {
            int col = wn + nt * 8 + t2;
            float v0 = acc[nt][half * 2 + 0] + bs[col];
            float v1 = acc[nt][half * 2 + 1] + bs[col + 1];
            *(float2*)(cp + col) = make_float2(v0, v1);
        }
    }
}

// ---------------- layer GEMM: cp.async pipelined, pre-split inputs ------------
// y==0: Cu = relu?(Suu@Wuu+buu) + relu?(Siu@Wiu+biu)   (dual-term, K=128 each)
// y==1: Ci = relu?(Sui@Wui+bui)
__global__ __launch_bounds__(256, 2) void layer_gemm_kernel(
    const uint32_t* __restrict__ Sh, const uint32_t* __restrict__ Sl,
    const uint32_t* __restrict__ Wh, const uint32_t* __restrict__ Wl,
    const float* __restrict__ buu, const float* __restrict__ biu,
    const float* __restrict__ bui,
    float* __restrict__ Cu, float* __restrict__ Ci, int layer, int doRelu)
{
    extern __shared__ char sm[];
    const uint32_t sbase = smem_u32(sm);
    const int tid = threadIdx.x, lane = tid & 31, wid = tid >> 5;
    const int blockRow = blockIdx.x * BMROWS;
    const int wm = (wid & 3) * 16;
    const int wn = (wid >> 2) * 64;

    int plane[2], widx[2], nterm;
    if (blockIdx.y == 0) {
        plane[0] = 0; widx[0] = layer * 3 + 0;   // uu
        plane[1] = 2; widx[1] = layer * 3 + 2;   // iu
        nterm = 2;
        if (tid < 128) {
            ((float*)(sm + SM_BIAS))[tid] = buu[tid];
            ((float*)(sm + SM_BIAS + 512))[tid] = biu[tid];
        }
    } else {
        plane[0] = 1; widx[0] = layer * 3 + 1;   // ui
        plane[1] = 1; widx[1] = layer * 3 + 1;
        nterm = 1;
        if (tid < 128) ((float*)(sm + SM_BIAS))[tid] = bui[tid];
    }
    float* C = (blockIdx.y == 0) ? Cu : Ci;

    float acc[8][4], out[8][4];
#pragma unroll
    for (int j = 0; j < 8; j++)
#pragma unroll
        for (int k = 0; k < 4; k++) { acc[j][k] = 0.f; out[j][k] = 0.f; }

    const int r8 = lane & 7, sel = lane >> 3;
    const int a_row = r8 + ((sel & 1) << 3);
    const int a_kb  = (sel >> 1) << 4;
    const int b_csel = sel >> 1;
    const int g = lane >> 2;
    const int t2 = (lane & 3) * 2;

    // issue cp.async loads for chunk ci into buf (ci&1); no blocking
    auto issue_load = [&](int ci) {
        const int term = ci >> 2;
        const int k0 = (ci & 3) * 32;
        const uint32_t* Ah = Sh + (size_t)plane[term] * NP;
        const uint32_t* Al = Sl + (size_t)plane[term] * NP;
        const uint32_t* Bh = Wh + (size_t)widx[term] * 8192;
        const uint32_t* Bl = Wl + (size_t)widx[term] * 8192;
        uint32_t sbuf = sbase + (ci & 1) * BUFSZ;
        // A tile
#pragma unroll
        for (int i = 0; i < 2; i++) {
            int idx = tid + i * 256;
            int row = idx >> 3, q = idx & 7;
            int gm = blockRow + row;
            int sz = (gm < NN) ? 8 : 0;
            size_t o = (size_t)gm * 64 + (k0 >> 1) + q * 2;
            uint32_t sa = sbuf + (uint32_t)row * 80 + q * 8;
            cp_async8(sa, Ah + o, sz);
            cp_async8(sa + ABUF, Al + o, sz);
        }
        // B tile with XOR chunk swizzle
#pragma unroll
        for (int i = 0; i < 4; i++) {
            int idx = tid + i * 256;
            int kk = idx >> 5, q = idx & 31;
            size_t go = (size_t)(k0 + kk) * 64 + q * 2;
            uint32_t o = (uint32_t)kk * 256 + ((((uint32_t)(q >> 1)) ^ (kk & 7)) << 4) + (q & 1) * 8;
            cp_async8(sbuf + 2 * ABUF + o, Bh + go, 8);
            cp_async8(sbuf + 2 * ABUF + BBUF + o, Bl + go, 8);
        }
        CP_COMMIT();
    };

    const int total = nterm * 4;
    issue_load(0);

    for (int ci = 0; ci < total; ci++) {
        CP_WAIT0();
        __syncthreads();                    // chunk ci data ready; all warps done with ci-1
        if (ci + 1 < total) issue_load(ci + 1);

        const uint32_t bufb = sbase + (ci & 1) * BUFSZ;
#pragma unroll
        for (int h = 0; h < 2; h++) {
            uint32_t ah[4], al[4], bf[4][4];
            {
                uint32_t aaddr = bufb + (wm + a_row) * 80 + h * 32 + a_kb;
                ldm_x4(ah, aaddr);
                ldm_x4(al, aaddr + ABUF);
            }
            const int kk = h * 16 + a_row;
            const uint32_t brow = bufb + 2 * ABUF + (uint32_t)kk * 256;
#pragma unroll
            for (int j = 0; j < 4; j++) {
                uint32_t chunk = (uint32_t)((wn >> 3) + j * 2 + b_csel) ^ (kk & 7);
                ldm_x4_t(bf[j], brow + chunk * 16);
            }
#pragma unroll
            for (int j = 0; j < 4; j++) {
                mma_bf16(acc[2 * j],     ah, bf[j][0], bf[j][1]);
                mma_bf16(acc[2 * j + 1], ah, bf[j][2], bf[j][3]);
                mma_bf16(acc[2 * j],     al, bf[j][0], bf[j][1]);
                mma_bf16(acc[2 * j + 1], al, bf[j][2], bf[j][3]);
            }
#pragma unroll
            for (int j = 0; j < 4; j++) {
                uint32_t chunk = (uint32_t)((wn >> 3) + j * 2 + b_csel) ^ (kk & 7);
                ldm_x4_t(bf[j], brow + BBUF + chunk * 16);
            }
#pragma unroll
            for (int j = 0; j < 4; j++) {
                mma_bf16(acc[2 * j],     ah, bf[j][0], bf[j][1]);
                mma_bf16(acc[2 * j + 1], ah, bf[j][2], bf[j][3]);
            }
        }

        if ((ci & 3) == 3) {
            // fold this term: out += maybe_relu(acc + bias[term]); reset acc
            const float* bt = (const float*)(sm + SM_BIAS + (ci >> 2) * 512);
#pragma unroll
            for (int nt = 0; nt < 8; nt++)
#pragma unroll
                for (int half = 0; half < 2; half++)
#pragma unroll
                    for (int j2 = 0; j2 < 2; j2++) {
                        int col = wn + nt * 8 + t2 + j2;
                        float v = acc[nt][half * 2 + j2] + bt[col];
                        if (doRelu) v = fmaxf(v, 0.f);
                        out[nt][half * 2 + j2] += v;
                        acc[nt][half * 2 + j2] = 0.f;
                    }
        }
    }

    // epilogue: write out
#pragma unroll
    for (int half = 0; half < 2; half++) {
        int row = blockRow + wm + g + half * 8;
        if (row >= NN) continue;
        float* cp = C + (size_t)row * 128;
#pragma unroll
        for (int nt = 0; nt < 8; nt++) {
            int col = wn + nt * 8 + t2;
            *(float2*)(cp + col) = make_float2(out[nt][half * 2 + 0],
                                               out[nt][half * 2 + 1]);
        }
    }
}

// ---------------- host orchestration -----------------------------------------
extern "C" void kernel_launch(void* const* d_in, const int* in_sizes, int n_in,
                              void* d_out, int out_size) {
    const float* feat_user = (const float*)d_in[0];
    const float* feat_item = (const float*)d_in[1];
    const int* src_uu = (const int*)d_in[2];
    const int* dst_uu = (const int*)d_in[3];
    const int* src_ui = (const int*)d_in[4];
    const int* dst_ui = (const int*)d_in[5];
    const int* src_iu = (const int*)d_in[6];
    const int* dst_iu = (const int*)d_in[7];
    const float* We_u = (const float*)d_in[8];
    const float* be_u = (const float*)d_in[9];
    const float* We_i = (const float*)d_in[10];
    const float* be_i = (const float*)d_in[11];
    const float* W[3][3];
    const float* B[3][3];
    for (int l = 0; l < 3; l++)
        for (int e = 0; e < 3; e++) {
            W[l][e] = (const float*)d_in[12 + l * 6 + e * 2];
            B[l][e] = (const float*)d_in[12 + l * 6 + e * 2 + 1];
        }

    float *hu, *hi, *deg;
    uint32_t *Sh, *Sl, *Wh, *Wl;
    int *degi, *off, *cur, *esrc, *bsum;
    cudaGetSymbolAddress((void**)&hu, g_hu);
    cudaGetSymbolAddress((void**)&hi, g_hi);
    cudaGetSymbolAddress((void**)&Sh, g_Sh);
    cudaGetSymbolAddress((void**)&Sl, g_Sl);
    cudaGetSymbolAddress((void**)&Wh, g_Wh);
    cudaGetSymbolAddress((void**)&Wl, g_Wl);
    cudaGetSymbolAddress((void**)&deg, g_deg);
    cudaGetSymbolAddress((void**)&degi, g_degi);
    cudaGetSymbolAddress((void**)&off, g_off);
    cudaGetSymbolAddress((void**)&cur, g_cur);
    cudaGetSymbolAddress((void**)&esrc, g_esrc);
    cudaGetSymbolAddress((void**)&bsum, g_bsum);
    float* out = (float*)d_out;

    cudaFuncSetAttribute(mma_embed_kernel,
                         cudaFuncAttributeMaxDynamicSharedMemorySize, TCSMEM);
    cudaFuncSetAttribute(layer_gemm_kernel,
                         cudaFuncAttributeMaxDynamicSharedMemorySize, TCSMEM);

    // ---- degree + CSR build + weight pre-split ----
    zero2_kernel<<<256, 256>>>(degi, 6 * NN, cur, 3 * NN);
    deg_count_kernel<<<(NE + 255) / 256, 256>>>(src_uu, dst_uu, src_ui, dst_ui,
                                                src_iu, dst_iu, degi);
    deg_finalize_kernel<<<(NN + 255) / 256, 256>>>(degi, deg);
    {
        dim3 g1(SCAN_NB, 3);
        scan_s1<<<g1, 256>>>(degi, off, bsum);
        scan_s2<<<1, 32>>>(bsum);
        dim3 g3((NN + 255) / 256, 3);
        scan_s3<<<g3, 256>>>(off, bsum);
    }
    {
        dim3 gf((NE + 255) / 256, 3);
        fill3_kernel<<<gf, 256>>>(src_uu, dst_uu, src_ui, dst_ui, src_iu, dst_iu,
                                  off, cur, esrc);
    }
    {
        WPtrs wp;
        for (int l = 0; l < 3; l++)
            for (int e = 0; e < 3; e++) wp.w[l * 3 + e] = W[l][e];
        dim3 gw((128 * 64 + 255) / 256, 9);
        wsplit_kernel<<<gw, 256>>>(wp, Wh, Wl);
    }

    int grid = (NN + BMROWS - 1) / BMROWS;

    // ---- embed (merged dense GEMM) ----
    {
        dim3 ge(grid, 2);
        mma_embed_kernel<<<ge, 256, TCSMEM>>>(feat_user, We_u, be_u,
                                              feat_item, We_i, be_i, hu, hi);
    }

    // ---- layers: 1 gather launch + 1 GEMM launch each ----
    int cur_pp = 0;
    for (int l = 0; l < 3; l++) {
        int relu = (l < 2) ? 1 : 0;
        float* hu_cur = hu + (size_t)cur_pp * NUH;
        float* hi_cur = hi + (size_t)cur_pp * NUH;
        float* hu_nxt = (l == 2) ? out : hu + (size_t)(1 - cur_pp) * NUH;
        float* hi_nxt = (l == 2) ? out + (size_t)NUH : hi + (size_t)(1 - cur_pp) * NUH;

        dim3 gg((NN + 7) / 8, 3);
        gather3_kernel<<<gg, 256>>>(hu_cur, hi_cur, deg, off, esrc, Sh, Sl);

        dim3 lg(grid, 2);
        layer_gemm_kernel<<<lg, 256, TCSMEM>>>(Sh, Sl, Wh, Wl,
                                               B[l][0], B[l][2], B[l][1],
                                               hu_nxt, hi_nxt, l, relu);
        cur_pp ^= 1;
    }
    (void)in_sizes; (void)n_in; (void)out_size;
}